// round 5
// baseline (speedup 1.0000x reference)
#include <cuda_runtime.h>

// ---------------- scratch (device globals; no runtime alloc) ----------------
__device__ float g_x1[4*8*128*128];
__device__ float g_x2[4*16*64*64];
__device__ float g_x3[4*32*32*32];
__device__ float g_x4[4*64*16*16];
__device__ float g_splat[4*64*256];
__device__ float g_l3[4*64*256];
__device__ float g_cvec[4*64];
__device__ float g_grid[4*12*8*256];   // [b][cc 12][lb 8][y 16][x 16]

// ============== generic 3x3 stride-2 conv (smem tile [pos][ci], padded) ======
template<int CI, int CIP, int COG, int CO_TOTAL, int IHW, int OHW, int TILE>
__device__ __forceinline__ void conv_run(const float* __restrict__ in,
        const float* __restrict__ w, const float* __restrict__ bias,
        float* __restrict__ out, float* s_in, int bb, int tile, int cog) {
    constexpr int IT = 2*TILE+1;
    constexpr int NT = OHW/TILE;
    constexpr int POS = TILE*TILE;
    constexpr int TPC = 256/COG;
    constexpr int OPT = POS/TPC;
    int ty0 = (tile/NT)*TILE, tx0 = (tile%NT)*TILE;
    int t = threadIdx.x;
    const float* inb = in + (size_t)bb*CI*IHW*IHW;
    for (int k = t; k < IT*IT*CI; k += 256) {
        int ci = k / (IT*IT);
        int i  = k % (IT*IT);
        int iy = 2*ty0 - 1 + i/IT;
        int ix = 2*tx0 - 1 + i%IT;
        float v = 0.f;
        if (iy >= 0 && iy < IHW && ix >= 0 && ix < IHW)
            v = __ldg(&inb[(size_t)ci*IHW*IHW + (size_t)iy*IHW + ix]);
        s_in[i*CIP + ci] = v;
    }
    __syncthreads();
    int co = cog*COG + t/TPC;
    int pbase = t % TPC;
    float acc[OPT];
    #pragma unroll
    for (int k = 0; k < OPT; k++) acc[k] = bias[co];
    const float* wc = w + co*CI*9;
    #pragma unroll 1
    for (int c0 = 0; c0 < CI; c0 += 4) {
        float4 wk[9];
        #pragma unroll
        for (int k = 0; k < 9; k++) {
            wk[k].x = wc[(c0+0)*9+k];
            wk[k].y = wc[(c0+1)*9+k];
            wk[k].z = wc[(c0+2)*9+k];
            wk[k].w = wc[(c0+3)*9+k];
        }
        #pragma unroll
        for (int k = 0; k < OPT; k++) {
            int p = pbase + k*TPC;
            int py = p/TILE, px = p%TILE;
            #pragma unroll
            for (int ky = 0; ky < 3; ky++)
            #pragma unroll
            for (int kx = 0; kx < 3; kx++) {
                float4 v = *(const float4*)&s_in[((2*py+ky)*IT + 2*px+kx)*CIP + c0];
                float4 wv = wk[ky*3+kx];
                acc[k] += v.x*wv.x + v.y*wv.y + v.z*wv.z + v.w*wv.w;
            }
        }
    }
    float* outb = out + (size_t)bb*CO_TOTAL*OHW*OHW;
    #pragma unroll
    for (int k = 0; k < OPT; k++) {
        int p = pbase + k*TPC;
        outb[(size_t)co*OHW*OHW + (size_t)(ty0+p/TILE)*OHW + tx0 + p%TILE] = fmaxf(acc[k], 0.f);
    }
}

// ============== conv1: fused bilinear downsample + 3x3 s2 conv ================
// low(ci,iy,ix) = 0.25*(im[4iy+1,4ix+1]+im[4iy+1,4ix+2]+im[4iy+2,4ix+1]+im[4iy+2,4ix+2])
// cols 4ix+1,4ix+2 are lanes .y/.z of the 16B-aligned float4 at column 4ix.
__global__ void __launch_bounds__(256) k_conv1(const float* __restrict__ im,
        const float* __restrict__ w, const float* __restrict__ bias) {
    constexpr int TILE = 8, IT = 17, NT = 16;
    constexpr int TPC = 32, OPT = 2;
    __shared__ float s_in[IT*IT*4];
    int bb = blockIdx.y;
    int tile = blockIdx.x;
    int ty0 = (tile/NT)*TILE, tx0 = (tile%NT)*TILE;
    int t = threadIdx.x;
    const float* imb = im + (size_t)bb * 3 * 1048576;
    for (int k = t; k < 289*3; k += 256) {
        int ci = k / 289, i = k % 289;
        int iy = 2*ty0 - 1 + i/IT;
        int ix = 2*tx0 - 1 + i%IT;
        float v = 0.f;
        if (iy >= 0 && iy < 256 && ix >= 0 && ix < 256) {
            const float4* p = (const float4*)(imb + (size_t)ci*1048576 + (size_t)(4*iy+1)*1024) + ix;
            float4 r1 = __ldg(p);
            float4 r2 = __ldg(p + 256);   // next image row
            v = 0.25f*(r1.y + r1.z + r2.y + r2.z);
        }
        s_in[i*4 + ci] = v;
    }
    __syncthreads();
    int co = t / TPC;
    int pbase = t % TPC;
    float acc[OPT];
    #pragma unroll
    for (int k = 0; k < OPT; k++) acc[k] = bias[co];
    const float* wc = w + co*3*9;
    float4 wk[9];
    #pragma unroll
    for (int k = 0; k < 9; k++) {
        wk[k].x = wc[0*9+k]; wk[k].y = wc[1*9+k]; wk[k].z = wc[2*9+k]; wk[k].w = 0.f;
    }
    #pragma unroll
    for (int k = 0; k < OPT; k++) {
        int p = pbase + k*TPC;
        int py = p/TILE, px = p%TILE;
        #pragma unroll
        for (int ky = 0; ky < 3; ky++)
        #pragma unroll
        for (int kx = 0; kx < 3; kx++) {
            float4 v = *(const float4*)&s_in[((2*py+ky)*IT + 2*px+kx)*4];
            float4 wv = wk[ky*3+kx];
            acc[k] += v.x*wv.x + v.y*wv.y + v.z*wv.z;
        }
    }
    float* outb = g_x1 + (size_t)bb*8*128*128;
    #pragma unroll
    for (int k = 0; k < OPT; k++) {
        int p = pbase + k*TPC;
        outb[(size_t)co*16384 + (size_t)(ty0+p/TILE)*128 + tx0 + p%TILE] = fmaxf(acc[k], 0.f);
    }
}

// ============== conv2..4 standalone ==========================================
__global__ void __launch_bounds__(256) k_conv2(const float* __restrict__ w,
                                               const float* __restrict__ b) {
    __shared__ float s_in[289*12];
    conv_run<8, 12, 16, 16, 128, 64, 8>(g_x1, w, b, g_x2, s_in,
                                        blockIdx.y, blockIdx.x, 0);
}
__global__ void __launch_bounds__(256) k_conv3(const float* __restrict__ w,
                                               const float* __restrict__ b) {
    __shared__ float s_in[289*20];
    conv_run<16, 20, 32, 32, 64, 32, 8>(g_x2, w, b, g_x3, s_in,
                                        blockIdx.y, blockIdx.x, 0);
}
__global__ void __launch_bounds__(256) k_conv4(const float* __restrict__ w,
                                               const float* __restrict__ b) {
    __shared__ float s_in[289*36];
    conv_run<32, 36, 16, 64, 32, 16, 8>(g_x3, w, b, g_x4, s_in,
                                        blockIdx.y, blockIdx.x & 3, blockIdx.x >> 2);
}

// ============== mid: splat + local 3-layer MLP, 16 positions/block ===========
__global__ void __launch_bounds__(256) k_mid(
        const float* __restrict__ spw, const float* __restrict__ spb,
        const float* __restrict__ val,
        const float* __restrict__ lw1, const float* __restrict__ lb1,
        const float* __restrict__ lw2, const float* __restrict__ lb2,
        const float* __restrict__ lw3, const float* __restrict__ lb3) {
    __shared__ float A[64*16], Bf[128*16], Cf[128*16];
    int bb = blockIdx.y;
    int pos0 = blockIdx.x * 16;
    int t = threadIdx.x;
    const float* x4 = g_x4 + bb*16384;
    float vb = val[bb];
    for (int o = t; o < 1024; o += 256) {
        int ch = o >> 4, p = o & 15;
        float acc = spb[ch] + vb;
        const float* wr = spw + ch*64;
        #pragma unroll 8
        for (int i = 0; i < 64; i++) acc = fmaf(wr[i], x4[i*256 + pos0 + p], acc);
        A[ch*16 + p] = acc;
        g_splat[(bb*64 + ch)*256 + pos0 + p] = acc;
    }
    __syncthreads();
    for (int o = t; o < 2048; o += 256) {
        int ch = o >> 4, p = o & 15;
        float acc = lb1[ch];
        const float* wr = lw1 + ch*64;
        #pragma unroll 8
        for (int i = 0; i < 64; i++) acc = fmaf(wr[i], A[i*16 + p], acc);
        Bf[ch*16 + p] = fmaxf(acc, 0.f);
    }
    __syncthreads();
    for (int o = t; o < 2048; o += 256) {
        int ch = o >> 4, p = o & 15;
        float acc = lb2[ch];
        const float* wr = lw2 + ch*128;
        #pragma unroll 8
        for (int i = 0; i < 128; i++) acc = fmaf(wr[i], Bf[i*16 + p], acc);
        Cf[ch*16 + p] = fmaxf(acc, 0.f);
    }
    __syncthreads();
    for (int o = t; o < 1024; o += 256) {
        int ch = o >> 4, p = o & 15;
        float acc = lb3[ch];
        const float* wr = lw3 + ch*128;
        #pragma unroll 8
        for (int i = 0; i < 128; i++) acc = fmaf(wr[i], Cf[i*16 + p], acc);
        g_l3[(bb*64 + ch)*256 + pos0 + p] = fmaxf(acc, 0.f);
    }
}

// ============== global path ===================================================
__global__ void __launch_bounds__(256) k_global(
        const float* __restrict__ cw,  const float* __restrict__ cb,
        const float* __restrict__ fw1, const float* __restrict__ fb1,
        const float* __restrict__ fw2, const float* __restrict__ fb2) {
    __shared__ float c4[4*64], cp[64], f1[64];
    int bb = blockIdx.x;
    int t = threadIdx.x;
    const float* sp = g_splat + bb*64*256;
    int oc = t >> 6, idx = t & 63;
    int gy2 = idx >> 3, gx2 = idx & 7;
    int pos = (2*gy2)*16 + 2*gx2;
    float acc = cb[oc];
    for (int i = 0; i < 64; i++) acc = fmaf(cw[oc*64+i], sp[i*256+pos], acc);
    c4[oc*64 + idx] = fmaxf(acc, 0.f);
    __syncthreads();
    if (t < 64) {
        int oc2 = t >> 4, py = (t >> 2) & 3, px = t & 3;
        cp[t] = 0.25f*(c4[oc2*64 + (2*py)*8 + 2*px]   + c4[oc2*64 + (2*py)*8 + 2*px+1] +
                       c4[oc2*64 + (2*py+1)*8 + 2*px] + c4[oc2*64 + (2*py+1)*8 + 2*px+1]);
    }
    __syncthreads();
    if (t < 64) {
        float a2 = fb1[t];
        for (int i = 0; i < 64; i++) a2 = fmaf(fw1[t*64+i], cp[i], a2);
        f1[t] = fmaxf(a2, 0.f);
    }
    __syncthreads();
    if (t < 64) {
        float a2 = fb2[t];
        for (int i = 0; i < 64; i++) a2 = fmaf(fw2[t*64+i], f1[i], a2);
        g_cvec[bb*64 + t] = fmaxf(a2, 0.f);
    }
}

// ============== fused = relu(c + loc); coeff pw 64->96; write grid ===========
__global__ void __launch_bounds__(256) k_coeff(const float* __restrict__ gw,
                                               const float* __restrict__ gb) {
    int tl = blockIdx.x;
    int bb = blockIdx.y;
    int t = threadIdx.x;
    __shared__ float fused[64*17];
    const float* l3p = g_l3 + bb*64*256;
    const float* cv = g_cvec + bb*64;
    for (int o = t; o < 1024; o += 256) {
        int ch = o >> 4, p = o & 15;
        fused[ch*17 + p] = fmaxf(cv[ch] + l3p[ch*256 + tl*16 + p], 0.f);
    }
    __syncthreads();
    for (int o = t; o < 1536; o += 256) {
        int och = o >> 4, p = o & 15;
        float acc = gb[och];
        const float* wr = gw + och*64;
        #pragma unroll 8
        for (int i = 0; i < 64; i++) acc = fmaf(wr[i], fused[i*17 + p], acc);
        int lb = och / 12, cc = och % 12;
        g_grid[((bb*12 + cc)*8 + lb)*256 + tl*16 + p] = acc;
    }
}

// ============== fused guide + bilateral slice =================================
__global__ void __launch_bounds__(256) k_slice(
        const float* __restrict__ im,
        const float* __restrict__ ccm_w, const float* __restrict__ ccm_b,
        const float* __restrict__ shifts, const float* __restrict__ slopes,
        const float* __restrict__ prw, const float* __restrict__ prb,
        float* __restrict__ out) {
    int bx = blockIdx.x, by = blockIdx.y, bb = blockIdx.z;
    __shared__ float sg[864];               // [cell(j*3+k)][z][c12]
    __shared__ float gy[4*72*4];            // per-group y-interp table
    __shared__ float s_ccm[9], s_ccmb[3], s_prw[3], s_prb[1];
    __shared__ float s_sh[48];
    __shared__ float s_cs[3][17], s_csh[3][17];
    int t = threadIdx.x;

    const float* gr = g_grid + (size_t)bb * 12 * 8 * 256;
    for (int k = t; k < 864; k += 256) {
        int c = k % 12;
        int z = (k / 12) % 8;
        int cell = k / 96;
        int j = cell / 3, kx = cell % 3;
        int yi = min(max(by - 1 + j, 0), 15);
        int xi = min(max(bx - 1 + kx, 0), 15);
        sg[k] = gr[(c*8 + z)*256 + yi*16 + xi];
    }
    if (t < 9)               s_ccm[t] = ccm_w[t];
    if (t >= 16 && t < 19)   s_ccmb[t-16] = ccm_b[t-16];
    if (t >= 32 && t < 80)   s_sh[t-32] = shifts[t-32];
    if (t >= 96 && t < 99)   s_prw[t-96] = prw[t-96];
    if (t == 102)            s_prb[0] = prb[0];
    if (t >= 104 && t < 107) {
        int c = t - 104;
        float cs = 0.f, csh = 0.f;
        s_cs[c][0] = 0.f; s_csh[c][0] = 0.f;
        #pragma unroll
        for (int k = 0; k < 16; k++) {
            float s = slopes[c*16+k], h = shifts[c*16+k];
            cs += s; csh += s*h;
            s_cs[c][k+1] = cs; s_csh[c][k+1] = csh;
        }
    }
    __syncthreads();

    int g = t >> 6;
    int lx = t & 63;
    int x = bx*64 + lx;
    float cxv = ((float)x + 0.5f) * (1.0f/64.0f) - 0.5f;
    float wx = cxv - floorf(cxv);
    int k0 = (int)floorf(cxv) - (bx - 1);
    const float* imb = im + (size_t)bb * 3 * 1048576;
    float* outb = out + (size_t)bb * 3 * 1048576;

    for (int r = 0; r < 16; r++) {
        int y = by*64 + g + 4*r;
        float cyv = ((float)y + 0.5f) * (1.0f/64.0f) - 0.5f;
        float wy = cyv - floorf(cyv);
        int j0 = (int)floorf(cyv) - (by - 1);

        for (int e = lx; e < 72; e += 64) {
            int cellx = e / 24;
            int z = (e / 3) % 8;
            int v = e % 3;
            float4 a = ((const float4*)sg)[((j0*3 + cellx)*8 + z)*3 + v];
            float4 b4 = ((const float4*)sg)[(((j0+1)*3 + cellx)*8 + z)*3 + v];
            float4 res;
            res.x = fmaf(wy, b4.x - a.x, a.x);
            res.y = fmaf(wy, b4.y - a.y, a.y);
            res.z = fmaf(wy, b4.z - a.z, a.z);
            res.w = fmaf(wy, b4.w - a.w, a.w);
            ((float4*)gy)[g*72 + e] = res;
        }
        asm volatile("bar.sync %0, %1;" :: "r"(g+1), "r"(64) : "memory");

        size_t poff = (size_t)y * 1024 + x;
        float i0 = __ldg(&imb[poff]);
        float i1 = __ldg(&imb[poff + 1048576]);
        float i2 = __ldg(&imb[poff + 2097152]);

        float q0 = s_ccmb[0] + s_ccm[0]*i0 + s_ccm[1]*i1 + s_ccm[2]*i2;
        float q1 = s_ccmb[1] + s_ccm[3]*i0 + s_ccm[4]*i1 + s_ccm[5]*i2;
        float q2 = s_ccmb[2] + s_ccm[6]*i0 + s_ccm[7]*i1 + s_ccm[8]*i2;
        float tt[3];
        float qv[3] = {q0, q1, q2};
        #pragma unroll
        for (int c = 0; c < 3; c++) {
            const float* H = &s_sh[c*16];
            float gv = qv[c];
            int p = (gv > H[7]) ? 8 : 0;
            p += (gv > H[p+3]) ? 4 : 0;
            p += (gv > H[p+1]) ? 2 : 0;
            p += (gv > H[p])   ? 1 : 0;
            p += (gv > H[p])   ? 1 : 0;
            tt[c] = fmaf(gv, s_cs[c][p], -s_csh[c][p]);
        }
        float gg = s_prb[0] + s_prw[0]*tt[0] + s_prw[1]*tt[1] + s_prw[2]*tt[2];
        float guide = fminf(fmaxf(gg, 0.f), 1.f);

        float cz = guide * 8.0f - 0.5f;
        float z0f = floorf(cz);
        float wz = cz - z0f;
        int z0 = (int)z0f;
        int zi0 = min(max(z0, 0), 7);
        int zi1 = min(max(z0 + 1, 0), 7);

        float w00 = (1.f-wx)*(1.f-wz), w01 = (1.f-wx)*wz;
        float w10 = wx*(1.f-wz),       w11 = wx*wz;

        const float4* T = (const float4*)gy;
        int bA = (g*3 + k0)*8;
        int bB = bA + 8;
        int iA0 = (bA + zi0)*3, iA1 = (bA + zi1)*3;
        int iB0 = (bB + zi0)*3, iB1 = (bB + zi1)*3;

        float a0,a1,a2,a3,a4,a5,a6,a7,a8,a9,a10,a11;
        {
            float4 v0 = T[iA0], v1 = T[iA1], v2 = T[iB0], v3 = T[iB1];
            a0 = w00*v0.x + w01*v1.x + w10*v2.x + w11*v3.x;
            a1 = w00*v0.y + w01*v1.y + w10*v2.y + w11*v3.y;
            a2 = w00*v0.z + w01*v1.z + w10*v2.z + w11*v3.z;
            a3 = w00*v0.w + w01*v1.w + w10*v2.w + w11*v3.w;
        }
        {
            float4 v0 = T[iA0+1], v1 = T[iA1+1], v2 = T[iB0+1], v3 = T[iB1+1];
            a4 = w00*v0.x + w01*v1.x + w10*v2.x + w11*v3.x;
            a5 = w00*v0.y + w01*v1.y + w10*v2.y + w11*v3.y;
            a6 = w00*v0.z + w01*v1.z + w10*v2.z + w11*v3.z;
            a7 = w00*v0.w + w01*v1.w + w10*v2.w + w11*v3.w;
        }
        {
            float4 v0 = T[iA0+2], v1 = T[iA1+2], v2 = T[iB0+2], v3 = T[iB1+2];
            a8  = w00*v0.x + w01*v1.x + w10*v2.x + w11*v3.x;
            a9  = w00*v0.y + w01*v1.y + w10*v2.y + w11*v3.y;
            a10 = w00*v0.z + w01*v1.z + w10*v2.z + w11*v3.z;
            a11 = w00*v0.w + w01*v1.w + w10*v2.w + w11*v3.w;
        }
        outb[poff]           = fmaf(a0, i0, fmaf(a1, i1, fmaf(a2,  i2, a3)));
        outb[poff + 1048576] = fmaf(a4, i0, fmaf(a5, i1, fmaf(a6,  i2, a7)));
        outb[poff + 2097152] = fmaf(a8, i0, fmaf(a9, i1, fmaf(a10, i2, a11)));

        asm volatile("bar.sync %0, %1;" :: "r"(g+1), "r"(64) : "memory");
    }
}

// ---------------- launcher ---------------------------------------------------
extern "C" void kernel_launch(void* const* d_in, const int* in_sizes, int n_in,
                              void* d_out, int out_size) {
    const float* image = (const float*)d_in[0];
    const float* val   = (const float*)d_in[1];
    const float* sw0 = (const float*)d_in[2];  const float* sb0 = (const float*)d_in[3];
    const float* sw1 = (const float*)d_in[4];  const float* sb1 = (const float*)d_in[5];
    const float* sw2 = (const float*)d_in[6];  const float* sb2 = (const float*)d_in[7];
    const float* sw3 = (const float*)d_in[8];  const float* sb3 = (const float*)d_in[9];
    const float* spw = (const float*)d_in[10]; const float* spb = (const float*)d_in[11];
    const float* lw1 = (const float*)d_in[12]; const float* lb1 = (const float*)d_in[13];
    const float* lw2 = (const float*)d_in[14]; const float* lb2 = (const float*)d_in[15];
    const float* lw3 = (const float*)d_in[16]; const float* lb3 = (const float*)d_in[17];
    const float* cw  = (const float*)d_in[18]; const float* cb  = (const float*)d_in[19];
    const float* fw1 = (const float*)d_in[20]; const float* fb1 = (const float*)d_in[21];
    const float* fw2 = (const float*)d_in[22]; const float* fb2 = (const float*)d_in[23];
    const float* gw  = (const float*)d_in[24]; const float* gb  = (const float*)d_in[25];
    const float* ccm_w = (const float*)d_in[26]; const float* ccm_b = (const float*)d_in[27];
    const float* shifts = (const float*)d_in[28];
    const float* slopes = (const float*)d_in[29];
    const float* prw = (const float*)d_in[30]; const float* prb = (const float*)d_in[31];
    float* out = (float*)d_out;

    k_conv1<<<dim3(256, 4), 256>>>(image, sw0, sb0);
    k_conv2<<<dim3(64, 4), 256>>>(sw1, sb1);
    k_conv3<<<dim3(16, 4), 256>>>(sw2, sb2);
    k_conv4<<<dim3(16, 4), 256>>>(sw3, sb3);
    k_mid<<<dim3(16, 4), 256>>>(spw, spb, val, lw1, lb1, lw2, lb2, lw3, lb3);
    k_global<<<4, 256>>>(cw, cb, fw1, fb1, fw2, fb2);
    k_coeff<<<dim3(16, 4), 256>>>(gw, gb);
    k_slice<<<dim3(16, 16, 4), 256>>>(image, ccm_w, ccm_b, shifts, slopes, prw, prb, out);
}

// round 6
// speedup vs baseline: 1.0746x; 1.0746x over previous
#include <cuda_runtime.h>

// ---------------- scratch (device globals; no runtime alloc) ----------------
__device__ float g_x1[4*8*128*128];
__device__ float g_x2[4*16*64*64];
__device__ float g_x3[4*32*32*32];
__device__ float g_x4[4*64*16*16];
__device__ float g_splat[4*64*256];
__device__ float g_l3[4*64*256];
__device__ float g_cvec[4*64];
__device__ float g_grid[4*12*8*256];   // [b][cc 12][lb 8][y 16][x 16]

// ============== generic 3x3 stride-2 conv (smem input tile + smem weights) ===
template<int CI, int CIP, int COG, int CO_TOTAL, int IHW, int OHW, int TILE>
__device__ __forceinline__ void conv_run(const float* __restrict__ in,
        const float* __restrict__ w, const float* __restrict__ bias,
        float* __restrict__ out, float* s_in, float* s_w,
        int bb, int tile, int cog) {
    constexpr int IT = 2*TILE+1;
    constexpr int NT = OHW/TILE;
    constexpr int POS = TILE*TILE;
    constexpr int TPC = 256/COG;
    constexpr int OPT = (POS + TPC - 1)/TPC;
    constexpr int NW = COG*CI*9;
    int ty0 = (tile/NT)*TILE, tx0 = (tile%NT)*TILE;
    int t = threadIdx.x;
    // weights for this cog group -> smem (coalesced)
    const float* wg = w + (size_t)cog*NW;
    #pragma unroll
    for (int k = t; k < NW; k += 256) s_w[k] = __ldg(&wg[k]);
    // input tile -> smem
    const float* inb = in + (size_t)bb*CI*IHW*IHW;
    #pragma unroll
    for (int k = t; k < IT*IT*CI; k += 256) {
        int ci = k / (IT*IT);
        int i  = k % (IT*IT);
        int iy = 2*ty0 - 1 + i/IT;
        int ix = 2*tx0 - 1 + i%IT;
        float v = 0.f;
        if (iy >= 0 && iy < IHW && ix >= 0 && ix < IHW)
            v = __ldg(&inb[(size_t)ci*IHW*IHW + (size_t)iy*IHW + ix]);
        s_in[i*CIP + ci] = v;
    }
    __syncthreads();
    int co = cog*COG + t/TPC;
    int pbase = t % TPC;
    float acc[OPT];
    #pragma unroll
    for (int k = 0; k < OPT; k++) acc[k] = bias[co];
    const float* wc = s_w + (t/TPC)*CI*9;
    #pragma unroll
    for (int c0 = 0; c0 < CI; c0 += 4) {
        float4 wk[9];
        #pragma unroll
        for (int k = 0; k < 9; k++) {
            wk[k].x = wc[(c0+0)*9+k];
            wk[k].y = wc[(c0+1)*9+k];
            wk[k].z = wc[(c0+2)*9+k];
            wk[k].w = wc[(c0+3)*9+k];
        }
        #pragma unroll
        for (int k = 0; k < OPT; k++) {
            int p = pbase + k*TPC;
            int py = p/TILE, px = p%TILE;
            #pragma unroll
            for (int ky = 0; ky < 3; ky++)
            #pragma unroll
            for (int kx = 0; kx < 3; kx++) {
                float4 v = *(const float4*)&s_in[((2*py+ky)*IT + 2*px+kx)*CIP + c0];
                float4 wv = wk[ky*3+kx];
                acc[k] += v.x*wv.x + v.y*wv.y + v.z*wv.z + v.w*wv.w;
            }
        }
    }
    float* outb = out + (size_t)bb*CO_TOTAL*OHW*OHW;
    #pragma unroll
    for (int k = 0; k < OPT; k++) {
        int p = pbase + k*TPC;
        outb[(size_t)co*OHW*OHW + (size_t)(ty0+p/TILE)*OHW + tx0 + p%TILE] = fmaxf(acc[k], 0.f);
    }
}

// ============== conv1: fused bilinear downsample + 3x3 s2 conv ================
__global__ void __launch_bounds__(256) k_conv1(const float* __restrict__ im,
        const float* __restrict__ w, const float* __restrict__ bias) {
    constexpr int TILE = 8, IT = 17, NT = 16;
    constexpr int TPC = 32, OPT = 2;
    __shared__ float s_in[IT*IT*4];
    __shared__ float s_w[8*3*9];
    int bb = blockIdx.y;
    int tile = blockIdx.x;
    int ty0 = (tile/NT)*TILE, tx0 = (tile%NT)*TILE;
    int t = threadIdx.x;
    if (t < 216) s_w[t] = __ldg(&w[t]);
    const float* imb = im + (size_t)bb * 3 * 1048576;
    #pragma unroll
    for (int k = t; k < 289*3; k += 256) {
        int ci = k / 289, i = k % 289;
        int iy = 2*ty0 - 1 + i/IT;
        int ix = 2*tx0 - 1 + i%IT;
        float v = 0.f;
        if (iy >= 0 && iy < 256 && ix >= 0 && ix < 256) {
            const float4* p = (const float4*)(imb + (size_t)ci*1048576 + (size_t)(4*iy+1)*1024) + ix;
            float4 r1 = __ldg(p);
            float4 r2 = __ldg(p + 256);
            v = 0.25f*(r1.y + r1.z + r2.y + r2.z);
        }
        s_in[i*4 + ci] = v;
    }
    __syncthreads();
    int co = t / TPC;
    int pbase = t % TPC;
    float acc[OPT];
    #pragma unroll
    for (int k = 0; k < OPT; k++) acc[k] = bias[co];
    const float* wc = s_w + co*27;
    float4 wk[9];
    #pragma unroll
    for (int k = 0; k < 9; k++) {
        wk[k].x = wc[k]; wk[k].y = wc[9+k]; wk[k].z = wc[18+k]; wk[k].w = 0.f;
    }
    #pragma unroll
    for (int k = 0; k < OPT; k++) {
        int p = pbase + k*TPC;
        int py = p/TILE, px = p%TILE;
        #pragma unroll
        for (int ky = 0; ky < 3; ky++)
        #pragma unroll
        for (int kx = 0; kx < 3; kx++) {
            float4 v = *(const float4*)&s_in[((2*py+ky)*IT + 2*px+kx)*4];
            float4 wv = wk[ky*3+kx];
            acc[k] += v.x*wv.x + v.y*wv.y + v.z*wv.z;
        }
    }
    float* outb = g_x1 + (size_t)bb*8*128*128;
    #pragma unroll
    for (int k = 0; k < OPT; k++) {
        int p = pbase + k*TPC;
        outb[(size_t)co*16384 + (size_t)(ty0+p/TILE)*128 + tx0 + p%TILE] = fmaxf(acc[k], 0.f);
    }
}

// ============== conv2..4 =====================================================
__global__ void __launch_bounds__(256) k_conv2(const float* __restrict__ w,
                                               const float* __restrict__ b) {
    __shared__ float s_in[289*12];
    __shared__ float s_w[16*8*9];
    conv_run<8, 12, 16, 16, 128, 64, 8>(g_x1, w, b, g_x2, s_in, s_w,
                                        blockIdx.y, blockIdx.x, 0);
}
__global__ void __launch_bounds__(256) k_conv3(const float* __restrict__ w,
                                               const float* __restrict__ b) {
    __shared__ float s_in[81*20];
    __shared__ float s_w[32*16*9];
    conv_run<16, 20, 32, 32, 64, 32, 4>(g_x2, w, b, g_x3, s_in, s_w,
                                        blockIdx.y, blockIdx.x, 0);
}
__global__ void __launch_bounds__(256) k_conv4(const float* __restrict__ w,
                                               const float* __restrict__ b) {
    __shared__ float s_in[81*36];
    __shared__ float s_w[16*32*9];
    conv_run<32, 36, 16, 64, 32, 16, 4>(g_x3, w, b, g_x4, s_in, s_w,
                                        blockIdx.y, blockIdx.x & 15, blockIdx.x >> 4);
}

// ============== mid: splat + local 3-layer MLP, 16 positions/block ===========
__global__ void __launch_bounds__(256) k_mid(
        const float* __restrict__ spw, const float* __restrict__ spb,
        const float* __restrict__ val,
        const float* __restrict__ lw1, const float* __restrict__ lb1,
        const float* __restrict__ lw2, const float* __restrict__ lb2,
        const float* __restrict__ lw3, const float* __restrict__ lb3) {
    __shared__ float A[64*16], Bf[128*16], Cf[128*16];
    int bb = blockIdx.y;
    int pos0 = blockIdx.x * 16;
    int t = threadIdx.x;
    const float* x4 = g_x4 + bb*16384;
    float vb = val[bb];
    for (int o = t; o < 1024; o += 256) {
        int ch = o >> 4, p = o & 15;
        float acc = spb[ch] + vb;
        const float* wr = spw + ch*64;
        #pragma unroll 8
        for (int i = 0; i < 64; i++) acc = fmaf(__ldg(&wr[i]), x4[i*256 + pos0 + p], acc);
        A[ch*16 + p] = acc;
        g_splat[(bb*64 + ch)*256 + pos0 + p] = acc;
    }
    __syncthreads();
    for (int o = t; o < 2048; o += 256) {
        int ch = o >> 3, p = o & 7;           // wait: 2048 outputs = 128ch x 16pos
        ch = o >> 4; p = o & 15;
        float acc = lb1[ch];
        const float* wr = lw1 + ch*64;
        #pragma unroll 8
        for (int i = 0; i < 64; i++) acc = fmaf(__ldg(&wr[i]), A[i*16 + p], acc);
        Bf[ch*16 + p] = fmaxf(acc, 0.f);
    }
    __syncthreads();
    for (int o = t; o < 2048; o += 256) {
        int ch = o >> 4, p = o & 15;
        float acc = lb2[ch];
        const float* wr = lw2 + ch*128;
        #pragma unroll 8
        for (int i = 0; i < 128; i++) acc = fmaf(__ldg(&wr[i]), Bf[i*16 + p], acc);
        Cf[ch*16 + p] = fmaxf(acc, 0.f);
    }
    __syncthreads();
    for (int o = t; o < 1024; o += 256) {
        int ch = o >> 4, p = o & 15;
        float acc = lb3[ch];
        const float* wr = lw3 + ch*128;
        #pragma unroll 8
        for (int i = 0; i < 128; i++) acc = fmaf(__ldg(&wr[i]), Cf[i*16 + p], acc);
        g_l3[(bb*64 + ch)*256 + pos0 + p] = fmaxf(acc, 0.f);
    }
}

// ============== global path ===================================================
__global__ void __launch_bounds__(256) k_global(
        const float* __restrict__ cw,  const float* __restrict__ cb,
        const float* __restrict__ fw1, const float* __restrict__ fb1,
        const float* __restrict__ fw2, const float* __restrict__ fb2) {
    __shared__ float c4[4*64], cp[64], f1[64];
    int bb = blockIdx.x;
    int t = threadIdx.x;
    const float* sp = g_splat + bb*64*256;
    int oc = t >> 6, idx = t & 63;
    int gy2 = idx >> 3, gx2 = idx & 7;
    int pos = (2*gy2)*16 + 2*gx2;
    float acc = cb[oc];
    for (int i = 0; i < 64; i++) acc = fmaf(cw[oc*64+i], sp[i*256+pos], acc);
    c4[oc*64 + idx] = fmaxf(acc, 0.f);
    __syncthreads();
    if (t < 64) {
        int oc2 = t >> 4, py = (t >> 2) & 3, px = t & 3;
        cp[t] = 0.25f*(c4[oc2*64 + (2*py)*8 + 2*px]   + c4[oc2*64 + (2*py)*8 + 2*px+1] +
                       c4[oc2*64 + (2*py+1)*8 + 2*px] + c4[oc2*64 + (2*py+1)*8 + 2*px+1]);
    }
    __syncthreads();
    if (t < 64) {
        float a2 = fb1[t];
        for (int i = 0; i < 64; i++) a2 = fmaf(fw1[t*64+i], cp[i], a2);
        f1[t] = fmaxf(a2, 0.f);
    }
    __syncthreads();
    if (t < 64) {
        float a2 = fb2[t];
        for (int i = 0; i < 64; i++) a2 = fmaf(fw2[t*64+i], f1[i], a2);
        g_cvec[bb*64 + t] = fmaxf(a2, 0.f);
    }
}

// ============== fused = relu(c + loc); coeff pw 64->96; write grid ===========
__global__ void __launch_bounds__(256) k_coeff(const float* __restrict__ gw,
                                               const float* __restrict__ gb) {
    int tl = blockIdx.x;
    int bb = blockIdx.y;
    int t = threadIdx.x;
    __shared__ float fused[64*17];
    const float* l3p = g_l3 + bb*64*256;
    const float* cv = g_cvec + bb*64;
    for (int o = t; o < 1024; o += 256) {
        int ch = o >> 4, p = o & 15;
        fused[ch*17 + p] = fmaxf(cv[ch] + l3p[ch*256 + tl*16 + p], 0.f);
    }
    __syncthreads();
    for (int o = t; o < 1536; o += 256) {
        int och = o >> 4, p = o & 15;
        float acc = gb[och];
        const float* wr = gw + och*64;
        #pragma unroll 8
        for (int i = 0; i < 64; i++) acc = fmaf(wr[i], fused[i*17 + p], acc);
        int lb = och / 12, cc = och % 12;
        g_grid[((bb*12 + cc)*8 + lb)*256 + tl*16 + p] = acc;
    }
}

// ============== fused guide + bilateral slice =================================
__global__ void __launch_bounds__(256) k_slice(
        const float* __restrict__ im,
        const float* __restrict__ ccm_w, const float* __restrict__ ccm_b,
        const float* __restrict__ shifts, const float* __restrict__ slopes,
        const float* __restrict__ prw, const float* __restrict__ prb,
        float* __restrict__ out) {
    int bx = blockIdx.x, by = blockIdx.y, bb = blockIdx.z;
    __shared__ float sg[864];               // [cell(j*3+k)][z][c12]
    __shared__ float gy[4*72*4];            // per-group y-interp table
    __shared__ float s_ccm[9], s_ccmb[3], s_prw[3], s_prb[1];
    __shared__ float s_sh[48];
    __shared__ float s_cs[3][17], s_csh[3][17];
    int t = threadIdx.x;

    const float* gr = g_grid + (size_t)bb * 12 * 8 * 256;
    for (int k = t; k < 864; k += 256) {
        int c = k % 12;
        int z = (k / 12) % 8;
        int cell = k / 96;
        int j = cell / 3, kx = cell % 3;
        int yi = min(max(by - 1 + j, 0), 15);
        int xi = min(max(bx - 1 + kx, 0), 15);
        sg[k] = gr[(c*8 + z)*256 + yi*16 + xi];
    }
    if (t < 9)               s_ccm[t] = ccm_w[t];
    if (t >= 16 && t < 19)   s_ccmb[t-16] = ccm_b[t-16];
    if (t >= 32 && t < 80)   s_sh[t-32] = shifts[t-32];
    if (t >= 96 && t < 99)   s_prw[t-96] = prw[t-96];
    if (t == 102)            s_prb[0] = prb[0];
    if (t >= 104 && t < 107) {
        int c = t - 104;
        float cs = 0.f, csh = 0.f;
        s_cs[c][0] = 0.f; s_csh[c][0] = 0.f;
        #pragma unroll
        for (int k = 0; k < 16; k++) {
            float s = slopes[c*16+k], h = shifts[c*16+k];
            cs += s; csh += s*h;
            s_cs[c][k+1] = cs; s_csh[c][k+1] = csh;
        }
    }
    __syncthreads();

    int g = t >> 6;
    int lx = t & 63;
    int x = bx*64 + lx;
    float cxv = ((float)x + 0.5f) * (1.0f/64.0f) - 0.5f;
    float wx = cxv - floorf(cxv);
    int k0 = (int)floorf(cxv) - (bx - 1);
    const float* imb = im + (size_t)bb * 3 * 1048576;
    float* outb = out + (size_t)bb * 3 * 1048576;

    for (int r = 0; r < 16; r++) {
        int y = by*64 + g + 4*r;
        float cyv = ((float)y + 0.5f) * (1.0f/64.0f) - 0.5f;
        float wy = cyv - floorf(cyv);
        int j0 = (int)floorf(cyv) - (by - 1);

        for (int e = lx; e < 72; e += 64) {
            int cellx = e / 24;
            int z = (e / 3) % 8;
            int v = e % 3;
            float4 a = ((const float4*)sg)[((j0*3 + cellx)*8 + z)*3 + v];
            float4 b4 = ((const float4*)sg)[(((j0+1)*3 + cellx)*8 + z)*3 + v];
            float4 res;
            res.x = fmaf(wy, b4.x - a.x, a.x);
            res.y = fmaf(wy, b4.y - a.y, a.y);
            res.z = fmaf(wy, b4.z - a.z, a.z);
            res.w = fmaf(wy, b4.w - a.w, a.w);
            ((float4*)gy)[g*72 + e] = res;
        }
        asm volatile("bar.sync %0, %1;" :: "r"(g+1), "r"(64) : "memory");

        size_t poff = (size_t)y * 1024 + x;
        float i0 = __ldg(&imb[poff]);
        float i1 = __ldg(&imb[poff + 1048576]);
        float i2 = __ldg(&imb[poff + 2097152]);

        float q0 = s_ccmb[0] + s_ccm[0]*i0 + s_ccm[1]*i1 + s_ccm[2]*i2;
        float q1 = s_ccmb[1] + s_ccm[3]*i0 + s_ccm[4]*i1 + s_ccm[5]*i2;
        float q2 = s_ccmb[2] + s_ccm[6]*i0 + s_ccm[7]*i1 + s_ccm[8]*i2;
        float tt[3];
        float qv[3] = {q0, q1, q2};
        #pragma unroll
        for (int c = 0; c < 3; c++) {
            const float* H = &s_sh[c*16];
            float gv = qv[c];
            int p = (gv > H[7]) ? 8 : 0;
            p += (gv > H[p+3]) ? 4 : 0;
            p += (gv > H[p+1]) ? 2 : 0;
            p += (gv > H[p])   ? 1 : 0;
            p += (gv > H[p])   ? 1 : 0;
            tt[c] = fmaf(gv, s_cs[c][p], -s_csh[c][p]);
        }
        float gg = s_prb[0] + s_prw[0]*tt[0] + s_prw[1]*tt[1] + s_prw[2]*tt[2];
        float guide = fminf(fmaxf(gg, 0.f), 1.f);

        float cz = guide * 8.0f - 0.5f;
        float z0f = floorf(cz);
        float wz = cz - z0f;
        int z0 = (int)z0f;
        int zi0 = min(max(z0, 0), 7);
        int zi1 = min(max(z0 + 1, 0), 7);

        float w00 = (1.f-wx)*(1.f-wz), w01 = (1.f-wx)*wz;
        float w10 = wx*(1.f-wz),       w11 = wx*wz;

        const float4* T = (const float4*)gy;
        int bA = (g*3 + k0)*8;
        int bB = bA + 8;
        int iA0 = (bA + zi0)*3, iA1 = (bA + zi1)*3;
        int iB0 = (bB + zi0)*3, iB1 = (bB + zi1)*3;

        float a0,a1,a2,a3,a4,a5,a6,a7,a8,a9,a10,a11;
        {
            float4 v0 = T[iA0], v1 = T[iA1], v2 = T[iB0], v3 = T[iB1];
            a0 = w00*v0.x + w01*v1.x + w10*v2.x + w11*v3.x;
            a1 = w00*v0.y + w01*v1.y + w10*v2.y + w11*v3.y;
            a2 = w00*v0.z + w01*v1.z + w10*v2.z + w11*v3.z;
            a3 = w00*v0.w + w01*v1.w + w10*v2.w + w11*v3.w;
        }
        {
            float4 v0 = T[iA0+1], v1 = T[iA1+1], v2 = T[iB0+1], v3 = T[iB1+1];
            a4 = w00*v0.x + w01*v1.x + w10*v2.x + w11*v3.x;
            a5 = w00*v0.y + w01*v1.y + w10*v2.y + w11*v3.y;
            a6 = w00*v0.z + w01*v1.z + w10*v2.z + w11*v3.z;
            a7 = w00*v0.w + w01*v1.w + w10*v2.w + w11*v3.w;
        }
        {
            float4 v0 = T[iA0+2], v1 = T[iA1+2], v2 = T[iB0+2], v3 = T[iB1+2];
            a8  = w00*v0.x + w01*v1.x + w10*v2.x + w11*v3.x;
            a9  = w00*v0.y + w01*v1.y + w10*v2.y + w11*v3.y;
            a10 = w00*v0.z + w01*v1.z + w10*v2.z + w11*v3.z;
            a11 = w00*v0.w + w01*v1.w + w10*v2.w + w11*v3.w;
        }
        outb[poff]           = fmaf(a0, i0, fmaf(a1, i1, fmaf(a2,  i2, a3)));
        outb[poff + 1048576] = fmaf(a4, i0, fmaf(a5, i1, fmaf(a6,  i2, a7)));
        outb[poff + 2097152] = fmaf(a8, i0, fmaf(a9, i1, fmaf(a10, i2, a11)));

        asm volatile("bar.sync %0, %1;" :: "r"(g+1), "r"(64) : "memory");
    }
}

// ---------------- launcher ---------------------------------------------------
extern "C" void kernel_launch(void* const* d_in, const int* in_sizes, int n_in,
                              void* d_out, int out_size) {
    const float* image = (const float*)d_in[0];
    const float* val   = (const float*)d_in[1];
    const float* sw0 = (const float*)d_in[2];  const float* sb0 = (const float*)d_in[3];
    const float* sw1 = (const float*)d_in[4];  const float* sb1 = (const float*)d_in[5];
    const float* sw2 = (const float*)d_in[6];  const float* sb2 = (const float*)d_in[7];
    const float* sw3 = (const float*)d_in[8];  const float* sb3 = (const float*)d_in[9];
    const float* spw = (const float*)d_in[10]; const float* spb = (const float*)d_in[11];
    const float* lw1 = (const float*)d_in[12]; const float* lb1 = (const float*)d_in[13];
    const float* lw2 = (const float*)d_in[14]; const float* lb2 = (const float*)d_in[15];
    const float* lw3 = (const float*)d_in[16]; const float* lb3 = (const float*)d_in[17];
    const float* cw  = (const float*)d_in[18]; const float* cb  = (const float*)d_in[19];
    const float* fw1 = (const float*)d_in[20]; const float* fb1 = (const float*)d_in[21];
    const float* fw2 = (const float*)d_in[22]; const float* fb2 = (const float*)d_in[23];
    const float* gw  = (const float*)d_in[24]; const float* gb  = (const float*)d_in[25];
    const float* ccm_w = (const float*)d_in[26]; const float* ccm_b = (const float*)d_in[27];
    const float* shifts = (const float*)d_in[28];
    const float* slopes = (const float*)d_in[29];
    const float* prw = (const float*)d_in[30]; const float* prb = (const float*)d_in[31];
    float* out = (float*)d_out;

    k_conv1<<<dim3(256, 4), 256>>>(image, sw0, sb0);
    k_conv2<<<dim3(64, 4), 256>>>(sw1, sb1);
    k_conv3<<<dim3(64, 4), 256>>>(sw2, sb2);
    k_conv4<<<dim3(64, 4), 256>>>(sw3, sb3);
    k_mid<<<dim3(16, 4), 256>>>(spw, spb, val, lw1, lb1, lw2, lb2, lw3, lb3);
    k_global<<<4, 256>>>(cw, cb, fw1, fb1, fw2, fb2);
    k_coeff<<<dim3(16, 4), 256>>>(gw, gb);
    k_slice<<<dim3(16, 16, 4), 256>>>(image, ccm_w, ccm_b, shifts, slopes, prw, prb, out);
}

// round 7
// speedup vs baseline: 1.4513x; 1.3506x over previous
#include <cuda_runtime.h>

// ---------------- scratch (device globals; no runtime alloc) ----------------
__device__ float g_x1[4*8*128*128];
__device__ float g_x2[4*16*64*64];
__device__ float g_x3[4*32*32*32];
__device__ float g_x4[4*64*16*16];
__device__ float g_splat[4*64*256];
__device__ float g_l3[4*64*256];
__device__ float g_cvec[4*64];
__device__ float g_grid[4*12*8*256];   // [b][cc 12][lb 8][y 16][x 16]

// ============== generic 3x3 stride-2 conv =====================================
// smem: input tile [i][ci] (CIP padded), weights transposed [co][tap][ci]
// thread = (pos, co-group of CO_PER); weight LDS broadcast across lanes.
template<int CI, int COG, int CO_TOTAL, int IHW, int OHW, int TILE, int THREADS>
__device__ __forceinline__ void conv_run(const float* __restrict__ in,
        const float* __restrict__ w, const float* __restrict__ bias,
        float* __restrict__ out, float* __restrict__ s_in, float* __restrict__ s_w,
        int bb, int tile, int cog) {
    constexpr int IT  = 2*TILE+1;
    constexpr int NT  = OHW/TILE;
    constexpr int POS = TILE*TILE;
    constexpr int CIP = CI + 4;
    constexpr int CO_PER = COG*POS/THREADS;
    constexpr int NW  = COG*CI*9;
    int ty0 = (tile/NT)*TILE, tx0 = (tile%NT)*TILE;
    int t = threadIdx.x;

    // weights -> smem, transposed to [co][tap(9)][ci]
    const float* wg = w + (size_t)cog*NW;
    for (int idx = t; idx < NW; idx += THREADS) {
        int co = idx / (CI*9);
        int rem = idx % (CI*9);
        int ci = rem / 9, kk = rem % 9;
        s_w[(co*9 + kk)*CI + ci] = __ldg(&wg[idx]);
    }
    // input tile -> smem [i][ci]
    const float* inb = in + (size_t)bb*CI*IHW*IHW;
    for (int k = t; k < IT*IT*CI; k += THREADS) {
        int ci = k / (IT*IT);
        int i  = k % (IT*IT);
        int iy = 2*ty0 - 1 + i/IT;
        int ix = 2*tx0 - 1 + i%IT;
        float v = 0.f;
        if (iy >= 0 && iy < IHW && ix >= 0 && ix < IHW)
            v = __ldg(&inb[(size_t)ci*IHW*IHW + (size_t)iy*IHW + ix]);
        s_in[i*CIP + ci] = v;
    }
    __syncthreads();

    int pos = t % POS;
    int coq = t / POS;
    int py = pos / TILE, px = pos % TILE;
    float acc[CO_PER];
    #pragma unroll
    for (int j = 0; j < CO_PER; j++) acc[j] = bias[cog*COG + coq*CO_PER + j];

    #pragma unroll
    for (int c0 = 0; c0 < CI; c0 += 4) {
        #pragma unroll
        for (int ky = 0; ky < 3; ky++) {
            const float* rp = s_in + ((2*py+ky)*IT + 2*px)*CIP + c0;
            float4 i0 = *(const float4*)(rp);
            float4 i1 = *(const float4*)(rp + CIP);
            float4 i2 = *(const float4*)(rp + 2*CIP);
            #pragma unroll
            for (int j = 0; j < CO_PER; j++) {
                const float* wb = s_w + ((coq*CO_PER + j)*9 + ky*3)*CI + c0;
                float4 w0 = *(const float4*)(wb);
                float4 w1 = *(const float4*)(wb + CI);
                float4 w2 = *(const float4*)(wb + 2*CI);
                acc[j] += i0.x*w0.x + i0.y*w0.y + i0.z*w0.z + i0.w*w0.w
                        + i1.x*w1.x + i1.y*w1.y + i1.z*w1.z + i1.w*w1.w
                        + i2.x*w2.x + i2.y*w2.y + i2.z*w2.z + i2.w*w2.w;
            }
        }
    }
    #pragma unroll
    for (int j = 0; j < CO_PER; j++) {
        int co = cog*COG + coq*CO_PER + j;
        out[(size_t)(bb*CO_TOTAL + co)*OHW*OHW + (size_t)(ty0+py)*OHW + tx0+px]
            = fmaxf(acc[j], 0.f);
    }
}

// ============== conv1: fused bilinear downsample + 3x3 s2 conv ================
__global__ void __launch_bounds__(256) k_conv1(const float* __restrict__ im,
        const float* __restrict__ w, const float* __restrict__ bias) {
    constexpr int TILE = 8, IT = 17, NT = 16;
    constexpr int TPC = 32, OPT = 2;
    __shared__ float s_in[IT*IT*4];
    __shared__ float s_w[8*3*9];
    int bb = blockIdx.y;
    int tile = blockIdx.x;
    int ty0 = (tile/NT)*TILE, tx0 = (tile%NT)*TILE;
    int t = threadIdx.x;
    if (t < 216) s_w[t] = __ldg(&w[t]);
    const float* imb = im + (size_t)bb * 3 * 1048576;
    for (int k = t; k < 289*3; k += 256) {
        int ci = k / 289, i = k % 289;
        int iy = 2*ty0 - 1 + i/IT;
        int ix = 2*tx0 - 1 + i%IT;
        float v = 0.f;
        if (iy >= 0 && iy < 256 && ix >= 0 && ix < 256) {
            const float4* p = (const float4*)(imb + (size_t)ci*1048576 + (size_t)(4*iy+1)*1024) + ix;
            float4 r1 = __ldg(p);
            float4 r2 = __ldg(p + 256);
            v = 0.25f*(r1.y + r1.z + r2.y + r2.z);
        }
        s_in[i*4 + ci] = v;
    }
    __syncthreads();
    int co = t / TPC;
    int pbase = t % TPC;
    float acc[OPT];
    #pragma unroll
    for (int k = 0; k < OPT; k++) acc[k] = bias[co];
    const float* wc = s_w + co*27;
    float4 wk[9];
    #pragma unroll
    for (int k = 0; k < 9; k++) {
        wk[k].x = wc[k]; wk[k].y = wc[9+k]; wk[k].z = wc[18+k]; wk[k].w = 0.f;
    }
    #pragma unroll
    for (int k = 0; k < OPT; k++) {
        int p = pbase + k*TPC;
        int py = p/TILE, px = p%TILE;
        #pragma unroll
        for (int ky = 0; ky < 3; ky++)
        #pragma unroll
        for (int kx = 0; kx < 3; kx++) {
            float4 v = *(const float4*)&s_in[((2*py+ky)*IT + 2*px+kx)*4];
            float4 wv = wk[ky*3+kx];
            acc[k] += v.x*wv.x + v.y*wv.y + v.z*wv.z;
        }
    }
    float* outb = g_x1 + (size_t)bb*8*128*128;
    #pragma unroll
    for (int k = 0; k < OPT; k++) {
        int p = pbase + k*TPC;
        outb[(size_t)co*16384 + (size_t)(ty0+p/TILE)*128 + tx0 + p%TILE] = fmaxf(acc[k], 0.f);
    }
}

// ============== conv2..4 =====================================================
__global__ void __launch_bounds__(256) k_conv2(const float* __restrict__ w,
                                               const float* __restrict__ b) {
    __shared__ float s_in[289*12];
    __shared__ float s_w[16*9*8];
    conv_run<8, 16, 16, 128, 64, 8, 256>(g_x1, w, b, g_x2, s_in, s_w,
                                         blockIdx.z, blockIdx.x, blockIdx.y);
}
__global__ void __launch_bounds__(256) k_conv3(const float* __restrict__ w,
                                               const float* __restrict__ b) {
    __shared__ float s_in[289*20];
    __shared__ float s_w[16*9*16];
    conv_run<16, 16, 32, 64, 32, 8, 256>(g_x2, w, b, g_x3, s_in, s_w,
                                         blockIdx.z, blockIdx.x, blockIdx.y);
}
__global__ void __launch_bounds__(128) k_conv4(const float* __restrict__ w,
                                               const float* __restrict__ b) {
    __shared__ float s_in[81*36];
    __shared__ float s_w[16*9*32];
    conv_run<32, 16, 64, 32, 16, 4, 128>(g_x3, w, b, g_x4, s_in, s_w,
                                         blockIdx.z, blockIdx.x, blockIdx.y);
}

// ============== mid: splat + local MLP, 8 positions/block, smem weights ======
__global__ void __launch_bounds__(256) k_mid(
        const float* __restrict__ spw, const float* __restrict__ spb,
        const float* __restrict__ val,
        const float* __restrict__ lw1, const float* __restrict__ lb1,
        const float* __restrict__ lw2, const float* __restrict__ lb2,
        const float* __restrict__ lw3, const float* __restrict__ lb3) {
    __shared__ float s_w[8192];                 // 32 KB weight stage
    __shared__ float As[8*68], A2[8*68];        // acts transposed [p][ch]
    __shared__ float Bf[8*132], Cf[8*132];
    int bb = blockIdx.y;
    int pos0 = blockIdx.x * 8;
    int t = threadIdx.x;
    int p = t & 7, oct = t >> 3;                // 32 octs

    // stage spw (4096) + load x4 tile transposed
    for (int i = t*4; i < 4096; i += 1024)
        *(float4*)&s_w[i] = __ldg((const float4*)&spw[i]);
    for (int i = t; i < 512; i += 256) {
        int ci = i >> 3, pp = i & 7;
        As[pp*68 + ci] = __ldg(&g_x4[bb*16384 + ci*256 + pos0 + pp]);
    }
    __syncthreads();
    float vb = __ldg(&val[bb]);

    // splat (NO relu): 2 ch/thread
    #pragma unroll
    for (int j = 0; j < 2; j++) {
        int ch = oct*2 + j;
        float acc = __ldg(&spb[ch]) + vb;
        #pragma unroll
        for (int i = 0; i < 64; i += 4) {
            float4 a = *(const float4*)&As[p*68 + i];
            float4 wv = *(const float4*)&s_w[ch*64 + i];
            acc += a.x*wv.x + a.y*wv.y + a.z*wv.z + a.w*wv.w;
        }
        A2[p*68 + ch] = acc;
        g_splat[(bb*64 + ch)*256 + pos0 + p] = acc;
    }
    __syncthreads();

    // l1: 64->128, 4 ch/thread
    for (int i = t*4; i < 8192; i += 1024)
        *(float4*)&s_w[i] = __ldg((const float4*)&lw1[i]);
    __syncthreads();
    #pragma unroll
    for (int j = 0; j < 4; j++) {
        int ch = oct*4 + j;
        float acc = __ldg(&lb1[ch]);
        #pragma unroll
        for (int i = 0; i < 64; i += 4) {
            float4 a = *(const float4*)&A2[p*68 + i];
            float4 wv = *(const float4*)&s_w[ch*64 + i];
            acc += a.x*wv.x + a.y*wv.y + a.z*wv.z + a.w*wv.w;
        }
        Bf[p*132 + ch] = fmaxf(acc, 0.f);
    }
    __syncthreads();

    // l2: 128->128, two weight passes of 64 rows
    for (int half = 0; half < 2; half++) {
        for (int i = t*4; i < 8192; i += 1024)
            *(float4*)&s_w[i] = __ldg((const float4*)&lw2[half*8192 + i]);
        __syncthreads();
        if ((oct >> 4) == half) {
            int octl = oct & 15;
            #pragma unroll
            for (int j = 0; j < 4; j++) {
                int ch = half*64 + octl*4 + j;
                float acc = __ldg(&lb2[ch]);
                #pragma unroll
                for (int i = 0; i < 128; i += 4) {
                    float4 a = *(const float4*)&Bf[p*132 + i];
                    float4 wv = *(const float4*)&s_w[(octl*4 + j)*128 + i];
                    acc += a.x*wv.x + a.y*wv.y + a.z*wv.z + a.w*wv.w;
                }
                Cf[p*132 + ch] = fmaxf(acc, 0.f);
            }
        }
        __syncthreads();
    }

    // l3: 128->64, 2 ch/thread
    for (int i = t*4; i < 8192; i += 1024)
        *(float4*)&s_w[i] = __ldg((const float4*)&lw3[i]);
    __syncthreads();
    #pragma unroll
    for (int j = 0; j < 2; j++) {
        int ch = oct*2 + j;
        float acc = __ldg(&lb3[ch]);
        #pragma unroll
        for (int i = 0; i < 128; i += 4) {
            float4 a = *(const float4*)&Cf[p*132 + i];
            float4 wv = *(const float4*)&s_w[ch*128 + i];
            acc += a.x*wv.x + a.y*wv.y + a.z*wv.z + a.w*wv.w;
        }
        g_l3[(bb*64 + ch)*256 + pos0 + p] = fmaxf(acc, 0.f);
    }
}

// ============== global path ===================================================
__global__ void __launch_bounds__(256) k_global(
        const float* __restrict__ cw,  const float* __restrict__ cb,
        const float* __restrict__ fw1, const float* __restrict__ fb1,
        const float* __restrict__ fw2, const float* __restrict__ fb2) {
    __shared__ float c4[4*64], cp[64], f1[64];
    int bb = blockIdx.x;
    int t = threadIdx.x;
    const float* sp = g_splat + bb*64*256;
    int oc = t >> 6, idx = t & 63;
    int gy2 = idx >> 3, gx2 = idx & 7;
    int pos = (2*gy2)*16 + 2*gx2;
    float acc = cb[oc];
    for (int i = 0; i < 64; i++) acc = fmaf(cw[oc*64+i], sp[i*256+pos], acc);
    c4[oc*64 + idx] = fmaxf(acc, 0.f);
    __syncthreads();
    if (t < 64) {
        int oc2 = t >> 4, py = (t >> 2) & 3, px = t & 3;
        cp[t] = 0.25f*(c4[oc2*64 + (2*py)*8 + 2*px]   + c4[oc2*64 + (2*py)*8 + 2*px+1] +
                       c4[oc2*64 + (2*py+1)*8 + 2*px] + c4[oc2*64 + (2*py+1)*8 + 2*px+1]);
    }
    __syncthreads();
    if (t < 64) {
        float a2 = fb1[t];
        for (int i = 0; i < 64; i++) a2 = fmaf(fw1[t*64+i], cp[i], a2);
        f1[t] = fmaxf(a2, 0.f);
    }
    __syncthreads();
    if (t < 64) {
        float a2 = fb2[t];
        for (int i = 0; i < 64; i++) a2 = fmaf(fw2[t*64+i], f1[i], a2);
        g_cvec[bb*64 + t] = fmaxf(a2, 0.f);
    }
}

// ============== coeff: fused=relu(c+loc); pw 64->96; write grid ==============
__global__ void __launch_bounds__(256) k_coeff(const float* __restrict__ gw,
                                               const float* __restrict__ gb) {
    __shared__ float s_gw[6144];
    __shared__ float fused[16*68];              // [p][ch]
    int tl = blockIdx.x;
    int bb = blockIdx.y;
    int t = threadIdx.x;
    for (int i = t*4; i < 6144; i += 1024)
        *(float4*)&s_gw[i] = __ldg((const float4*)&gw[i]);
    const float* l3p = g_l3 + bb*64*256;
    const float* cv = g_cvec + bb*64;
    for (int o = t; o < 1024; o += 256) {
        int ch = o >> 4, p = o & 15;
        fused[p*68 + ch] = fmaxf(cv[ch] + l3p[ch*256 + tl*16 + p], 0.f);
    }
    __syncthreads();
    for (int o = t; o < 1536; o += 256) {
        int och = o >> 4, p = o & 15;
        float acc = __ldg(&gb[och]);
        #pragma unroll
        for (int i = 0; i < 64; i += 4) {
            float4 a = *(const float4*)&fused[p*68 + i];
            float4 wv = *(const float4*)&s_gw[och*64 + i];
            acc += a.x*wv.x + a.y*wv.y + a.z*wv.z + a.w*wv.w;
        }
        int lb = och / 12, cc = och % 12;
        g_grid[((bb*12 + cc)*8 + lb)*256 + tl*16 + p] = acc;
    }
}

// ============== fused guide + bilateral slice =================================
__global__ void __launch_bounds__(256) k_slice(
        const float* __restrict__ im,
        const float* __restrict__ ccm_w, const float* __restrict__ ccm_b,
        const float* __restrict__ shifts, const float* __restrict__ slopes,
        const float* __restrict__ prw, const float* __restrict__ prb,
        float* __restrict__ out) {
    int bx = blockIdx.x, by = blockIdx.y, bb = blockIdx.z;
    __shared__ float sg[864];               // [cell(j*3+k)][z][c12]
    __shared__ float gy[2][4*72*4];         // double-buffered y-interp tables
    __shared__ float s_ccm[9], s_ccmb[3], s_prw[3], s_prb[1];
    __shared__ float s_sh[48];
    __shared__ float s_cs[3][17], s_csh[3][17];
    int t = threadIdx.x;

    const float* gr = g_grid + (size_t)bb * 12 * 8 * 256;
    for (int k = t; k < 864; k += 256) {
        int c = k % 12;
        int z = (k / 12) % 8;
        int cell = k / 96;
        int j = cell / 3, kx = cell % 3;
        int yi = min(max(by - 1 + j, 0), 15);
        int xi = min(max(bx - 1 + kx, 0), 15);
        sg[k] = gr[(c*8 + z)*256 + yi*16 + xi];
    }
    if (t < 9)               s_ccm[t] = ccm_w[t];
    if (t >= 16 && t < 19)   s_ccmb[t-16] = ccm_b[t-16];
    if (t >= 32 && t < 80)   s_sh[t-32] = shifts[t-32];
    if (t >= 96 && t < 99)   s_prw[t-96] = prw[t-96];
    if (t == 102)            s_prb[0] = prb[0];
    if (t >= 104 && t < 107) {
        int c = t - 104;
        float cs = 0.f, csh = 0.f;
        s_cs[c][0] = 0.f; s_csh[c][0] = 0.f;
        #pragma unroll
        for (int k = 0; k < 16; k++) {
            float s = slopes[c*16+k], h = shifts[c*16+k];
            cs += s; csh += s*h;
            s_cs[c][k+1] = cs; s_csh[c][k+1] = csh;
        }
    }
    __syncthreads();

    int g = t >> 6;
    int lx = t & 63;
    int x = bx*64 + lx;
    float cxv = ((float)x + 0.5f) * (1.0f/64.0f) - 0.5f;
    float wx = cxv - floorf(cxv);
    int k0 = (int)floorf(cxv) - (bx - 1);
    const float* imb = im + (size_t)bb * 3 * 1048576;
    float* outb = out + (size_t)bb * 3 * 1048576;

    for (int r = 0; r < 16; r++) {
        int buf = r & 1;
        int y = by*64 + g + 4*r;
        float cyv = ((float)y + 0.5f) * (1.0f/64.0f) - 0.5f;
        float wy = cyv - floorf(cyv);
        int j0 = (int)floorf(cyv) - (by - 1);

        for (int e = lx; e < 72; e += 64) {
            int cellx = e / 24;
            int z = (e / 3) % 8;
            int v = e % 3;
            float4 a = ((const float4*)sg)[((j0*3 + cellx)*8 + z)*3 + v];
            float4 b4 = ((const float4*)sg)[(((j0+1)*3 + cellx)*8 + z)*3 + v];
            float4 res;
            res.x = fmaf(wy, b4.x - a.x, a.x);
            res.y = fmaf(wy, b4.y - a.y, a.y);
            res.z = fmaf(wy, b4.z - a.z, a.z);
            res.w = fmaf(wy, b4.w - a.w, a.w);
            ((float4*)gy[buf])[g*72 + e] = res;
        }
        asm volatile("bar.sync %0, %1;" :: "r"(g+1), "r"(64) : "memory");

        size_t poff = (size_t)y * 1024 + x;
        float i0 = __ldg(&imb[poff]);
        float i1 = __ldg(&imb[poff + 1048576]);
        float i2 = __ldg(&imb[poff + 2097152]);

        float q0 = s_ccmb[0] + s_ccm[0]*i0 + s_ccm[1]*i1 + s_ccm[2]*i2;
        float q1 = s_ccmb[1] + s_ccm[3]*i0 + s_ccm[4]*i1 + s_ccm[5]*i2;
        float q2 = s_ccmb[2] + s_ccm[6]*i0 + s_ccm[7]*i1 + s_ccm[8]*i2;
        float tt[3];
        float qv[3] = {q0, q1, q2};
        #pragma unroll
        for (int c = 0; c < 3; c++) {
            const float* H = &s_sh[c*16];
            float gv = qv[c];
            int p = (gv > H[7]) ? 8 : 0;
            p += (gv > H[p+3]) ? 4 : 0;
            p += (gv > H[p+1]) ? 2 : 0;
            p += (gv > H[p])   ? 1 : 0;
            p += (gv > H[p])   ? 1 : 0;
            tt[c] = fmaf(gv, s_cs[c][p], -s_csh[c][p]);
        }
        float gg = s_prb[0] + s_prw[0]*tt[0] + s_prw[1]*tt[1] + s_prw[2]*tt[2];
        float guide = fminf(fmaxf(gg, 0.f), 1.f);

        float cz = guide * 8.0f - 0.5f;
        float z0f = floorf(cz);
        float wz = cz - z0f;
        int z0 = (int)z0f;
        int zi0 = min(max(z0, 0), 7);
        int zi1 = min(max(z0 + 1, 0), 7);

        float w00 = (1.f-wx)*(1.f-wz), w01 = (1.f-wx)*wz;
        float w10 = wx*(1.f-wz),       w11 = wx*wz;

        const float4* T = (const float4*)gy[buf];
        int bA = (g*3 + k0)*8;
        int bB = bA + 8;
        int iA0 = (bA + zi0)*3, iA1 = (bA + zi1)*3;
        int iB0 = (bB + zi0)*3, iB1 = (bB + zi1)*3;

        float a0,a1,a2,a3,a4,a5,a6,a7,a8,a9,a10,a11;
        {
            float4 v0 = T[iA0], v1 = T[iA1], v2 = T[iB0], v3 = T[iB1];
            a0 = w00*v0.x + w01*v1.x + w10*v2.x + w11*v3.x;
            a1 = w00*v0.y + w01*v1.y + w10*v2.y + w11*v3.y;
            a2 = w00*v0.z + w01*v1.z + w10*v2.z + w11*v3.z;
            a3 = w00*v0.w + w01*v1.w + w10*v2.w + w11*v3.w;
        }
        {
            float4 v0 = T[iA0+1], v1 = T[iA1+1], v2 = T[iB0+1], v3 = T[iB1+1];
            a4 = w00*v0.x + w01*v1.x + w10*v2.x + w11*v3.x;
            a5 = w00*v0.y + w01*v1.y + w10*v2.y + w11*v3.y;
            a6 = w00*v0.z + w01*v1.z + w10*v2.z + w11*v3.z;
            a7 = w00*v0.w + w01*v1.w + w10*v2.w + w11*v3.w;
        }
        {
            float4 v0 = T[iA0+2], v1 = T[iA1+2], v2 = T[iB0+2], v3 = T[iB1+2];
            a8  = w00*v0.x + w01*v1.x + w10*v2.x + w11*v3.x;
            a9  = w00*v0.y + w01*v1.y + w10*v2.y + w11*v3.y;
            a10 = w00*v0.z + w01*v1.z + w10*v2.z + w11*v3.z;
            a11 = w00*v0.w + w01*v1.w + w10*v2.w + w11*v3.w;
        }
        outb[poff]           = fmaf(a0, i0, fmaf(a1, i1, fmaf(a2,  i2, a3)));
        outb[poff + 1048576] = fmaf(a4, i0, fmaf(a5, i1, fmaf(a6,  i2, a7)));
        outb[poff + 2097152] = fmaf(a8, i0, fmaf(a9, i1, fmaf(a10, i2, a11)));
        // no second barrier: next iter writes the other gy buffer; the
        // bar.sync at iter r+1 orders consume(r) before build(r+2).
    }
}

// ---------------- launcher ---------------------------------------------------
extern "C" void kernel_launch(void* const* d_in, const int* in_sizes, int n_in,
                              void* d_out, int out_size) {
    const float* image = (const float*)d_in[0];
    const float* val   = (const float*)d_in[1];
    const float* sw0 = (const float*)d_in[2];  const float* sb0 = (const float*)d_in[3];
    const float* sw1 = (const float*)d_in[4];  const float* sb1 = (const float*)d_in[5];
    const float* sw2 = (const float*)d_in[6];  const float* sb2 = (const float*)d_in[7];
    const float* sw3 = (const float*)d_in[8];  const float* sb3 = (const float*)d_in[9];
    const float* spw = (const float*)d_in[10]; const float* spb = (const float*)d_in[11];
    const float* lw1 = (const float*)d_in[12]; const float* lb1 = (const float*)d_in[13];
    const float* lw2 = (const float*)d_in[14]; const float* lb2 = (const float*)d_in[15];
    const float* lw3 = (const float*)d_in[16]; const float* lb3 = (const float*)d_in[17];
    const float* cw  = (const float*)d_in[18]; const float* cb  = (const float*)d_in[19];
    const float* fw1 = (const float*)d_in[20]; const float* fb1 = (const float*)d_in[21];
    const float* fw2 = (const float*)d_in[22]; const float* fb2 = (const float*)d_in[23];
    const float* gw  = (const float*)d_in[24]; const float* gb  = (const float*)d_in[25];
    const float* ccm_w = (const float*)d_in[26]; const float* ccm_b = (const float*)d_in[27];
    const float* shifts = (const float*)d_in[28];
    const float* slopes = (const float*)d_in[29];
    const float* prw = (const float*)d_in[30]; const float* prb = (const float*)d_in[31];
    float* out = (float*)d_out;

    k_conv1<<<dim3(256, 4), 256>>>(image, sw0, sb0);
    k_conv2<<<dim3(64, 1, 4), 256>>>(sw1, sb1);
    k_conv3<<<dim3(16, 2, 4), 256>>>(sw2, sb2);
    k_conv4<<<dim3(16, 4, 4), 128>>>(sw3, sb3);
    k_mid<<<dim3(32, 4), 256>>>(spw, spb, val, lw1, lb1, lw2, lb2, lw3, lb3);
    k_global<<<4, 256>>>(cw, cb, fw1, fb1, fw2, fb2);
    k_coeff<<<dim3(16, 4), 256>>>(gw, gb);
    k_slice<<<dim3(16, 16, 4), 256>>>(image, ccm_w, ccm_b, shifts, slopes, prw, prb, out);
}

// round 8
// speedup vs baseline: 1.5146x; 1.0436x over previous
#include <cuda_runtime.h>

// ---------------- scratch (device globals; no runtime alloc) ----------------
__device__ float g_x1[4*8*128*128];
__device__ float g_x2[4*16*64*64];
__device__ float g_x3[4*32*32*32];
__device__ float g_x4[4*64*16*16];
__device__ float g_splat[4*64*256];
__device__ float g_l3[4*64*256];
__device__ float g_cvec[4*64];
__device__ float g_grid[4*12*8*256];   // [b][cc 12][lb 8][y 16][x 16]
__device__ float g_w2T[16*9*8];        // conv weights transposed [co][tap][ci]
__device__ float g_w3T[32*9*16];
__device__ float g_w4T[64*9*32];

// ============== prep: transpose conv weights to [co][tap][ci] ================
__global__ void k_prep(const float* __restrict__ w2, const float* __restrict__ w3,
                       const float* __restrict__ w4) {
    int t = blockIdx.x*256 + threadIdx.x;
    int stride = gridDim.x*256;
    for (int idx = t; idx < 1152; idx += stride) {       // conv2: co16 ci8
        int co = idx / 72, rem = idx % 72, ci = rem / 9, kk = rem % 9;
        g_w2T[(co*9 + kk)*8 + ci] = __ldg(&w2[idx]);
    }
    for (int idx = t; idx < 4608; idx += stride) {       // conv3: co32 ci16
        int co = idx / 144, rem = idx % 144, ci = rem / 9, kk = rem % 9;
        g_w3T[(co*9 + kk)*16 + ci] = __ldg(&w3[idx]);
    }
    for (int idx = t; idx < 18432; idx += stride) {      // conv4: co64 ci32
        int co = idx / 288, rem = idx % 288, ci = rem / 9, kk = rem % 9;
        g_w4T[(co*9 + kk)*32 + ci] = __ldg(&w4[idx]);
    }
}

// ============== generic 3x3 stride-2 conv =====================================
// smem: input tile [i][ci] (CIP padded), weights [co][tap][ci] (pre-transposed)
template<int CI, int COG, int CO_TOTAL, int IHW, int OHW, int TILE, int THREADS>
__device__ __forceinline__ void conv_run(const float* __restrict__ in,
        const float* __restrict__ wT, const float* __restrict__ bias,
        float* __restrict__ out, float* __restrict__ s_in, float* __restrict__ s_w,
        int bb, int tile, int cog) {
    constexpr int IT  = 2*TILE+1;
    constexpr int NT  = OHW/TILE;
    constexpr int POS = TILE*TILE;
    constexpr int CIP = CI + 4;
    constexpr int CO_PER = COG*POS/THREADS;
    constexpr int NW  = COG*CI*9;
    int ty0 = (tile/NT)*TILE, tx0 = (tile%NT)*TILE;
    int t = threadIdx.x;

    // weights: straight coalesced float4 copy (already transposed)
    const float* wg = wT + (size_t)cog*NW;
    #pragma unroll
    for (int i = t*4; i < NW; i += THREADS*4)
        *(float4*)&s_w[i] = __ldg((const float4*)&wg[i]);
    // input tile -> smem [i][ci]
    const float* inb = in + (size_t)bb*CI*IHW*IHW;
    #pragma unroll
    for (int k = t; k < IT*IT*CI; k += THREADS) {
        int ci = k / (IT*IT);
        int i  = k % (IT*IT);
        int iy = 2*ty0 - 1 + i/IT;
        int ix = 2*tx0 - 1 + i%IT;
        float v = 0.f;
        if (iy >= 0 && iy < IHW && ix >= 0 && ix < IHW)
            v = __ldg(&inb[(size_t)ci*IHW*IHW + (size_t)iy*IHW + ix]);
        s_in[i*CIP + ci] = v;
    }
    __syncthreads();

    int pos = t % POS;
    int coq = t / POS;
    int py = pos / TILE, px = pos % TILE;
    float acc[CO_PER];
    #pragma unroll
    for (int j = 0; j < CO_PER; j++) acc[j] = bias[cog*COG + coq*CO_PER + j];

    #pragma unroll
    for (int c0 = 0; c0 < CI; c0 += 4) {
        #pragma unroll
        for (int ky = 0; ky < 3; ky++) {
            const float* rp = s_in + ((2*py+ky)*IT + 2*px)*CIP + c0;
            float4 i0 = *(const float4*)(rp);
            float4 i1 = *(const float4*)(rp + CIP);
            float4 i2 = *(const float4*)(rp + 2*CIP);
            #pragma unroll
            for (int j = 0; j < CO_PER; j++) {
                const float* wb = s_w + ((coq*CO_PER + j)*9 + ky*3)*CI + c0;
                float4 w0 = *(const float4*)(wb);
                float4 w1 = *(const float4*)(wb + CI);
                float4 w2 = *(const float4*)(wb + 2*CI);
                acc[j] += i0.x*w0.x + i0.y*w0.y + i0.z*w0.z + i0.w*w0.w
                        + i1.x*w1.x + i1.y*w1.y + i1.z*w1.z + i1.w*w1.w
                        + i2.x*w2.x + i2.y*w2.y + i2.z*w2.z + i2.w*w2.w;
            }
        }
    }
    #pragma unroll
    for (int j = 0; j < CO_PER; j++) {
        int co = cog*COG + coq*CO_PER + j;
        out[(size_t)(bb*CO_TOTAL + co)*OHW*OHW + (size_t)(ty0+py)*OHW + tx0+px]
            = fmaxf(acc[j], 0.f);
    }
}

// ============== conv1: fused bilinear downsample + 3x3 s2 conv ================
__global__ void __launch_bounds__(256) k_conv1(const float* __restrict__ im,
        const float* __restrict__ w, const float* __restrict__ bias) {
    constexpr int TILE = 8, IT = 17, NT = 16;
    constexpr int TPC = 32, OPT = 2;
    __shared__ float s_in[IT*IT*4];
    __shared__ float s_w[8*3*9];
    int bb = blockIdx.y;
    int tile = blockIdx.x;
    int ty0 = (tile/NT)*TILE, tx0 = (tile%NT)*TILE;
    int t = threadIdx.x;
    if (t < 216) s_w[t] = __ldg(&w[t]);
    const float* imb = im + (size_t)bb * 3 * 1048576;
    #pragma unroll
    for (int k = t; k < 289*3; k += 256) {
        int ci = k / 289, i = k % 289;
        int iy = 2*ty0 - 1 + i/IT;
        int ix = 2*tx0 - 1 + i%IT;
        float v = 0.f;
        if (iy >= 0 && iy < 256 && ix >= 0 && ix < 256) {
            const float4* p = (const float4*)(imb + (size_t)ci*1048576 + (size_t)(4*iy+1)*1024) + ix;
            float4 r1 = __ldg(p);
            float4 r2 = __ldg(p + 256);
            v = 0.25f*(r1.y + r1.z + r2.y + r2.z);
        }
        s_in[i*4 + ci] = v;
    }
    __syncthreads();
    int co = t / TPC;
    int pbase = t % TPC;
    float acc[OPT];
    #pragma unroll
    for (int k = 0; k < OPT; k++) acc[k] = bias[co];
    const float* wc = s_w + co*27;
    float4 wk[9];
    #pragma unroll
    for (int k = 0; k < 9; k++) {
        wk[k].x = wc[k]; wk[k].y = wc[9+k]; wk[k].z = wc[18+k]; wk[k].w = 0.f;
    }
    #pragma unroll
    for (int k = 0; k < OPT; k++) {
        int p = pbase + k*TPC;
        int py = p/TILE, px = p%TILE;
        #pragma unroll
        for (int ky = 0; ky < 3; ky++)
        #pragma unroll
        for (int kx = 0; kx < 3; kx++) {
            float4 v = *(const float4*)&s_in[((2*py+ky)*IT + 2*px+kx)*4];
            float4 wv = wk[ky*3+kx];
            acc[k] += v.x*wv.x + v.y*wv.y + v.z*wv.z;
        }
    }
    float* outb = g_x1 + (size_t)bb*8*128*128;
    #pragma unroll
    for (int k = 0; k < OPT; k++) {
        int p = pbase + k*TPC;
        outb[(size_t)co*16384 + (size_t)(ty0+p/TILE)*128 + tx0 + p%TILE] = fmaxf(acc[k], 0.f);
    }
}

// ============== conv2..4 =====================================================
__global__ void __launch_bounds__(256) k_conv2(const float* __restrict__ b) {
    __shared__ float s_in[289*12];
    __shared__ float s_w[16*9*8];
    conv_run<8, 16, 16, 128, 64, 8, 256>(g_x1, g_w2T, b, g_x2, s_in, s_w,
                                         blockIdx.z, blockIdx.x, blockIdx.y);
}
__global__ void __launch_bounds__(256) k_conv3(const float* __restrict__ b) {
    __shared__ float s_in[289*20];
    __shared__ float s_w[16*9*16];
    conv_run<16, 16, 32, 64, 32, 8, 256>(g_x2, g_w3T, b, g_x3, s_in, s_w,
                                         blockIdx.z, blockIdx.x, blockIdx.y);
}
__global__ void __launch_bounds__(128) k_conv4(const float* __restrict__ b) {
    __shared__ float s_in[81*36];
    __shared__ float s_w[16*9*32];
    conv_run<32, 16, 64, 32, 16, 4, 128>(g_x3, g_w4T, b, g_x4, s_in, s_w,
                                         blockIdx.z, blockIdx.x, blockIdx.y);
}

// ============== mid: splat + local MLP, 8 positions/block, smem weights ======
__global__ void __launch_bounds__(256) k_mid(
        const float* __restrict__ spw, const float* __restrict__ spb,
        const float* __restrict__ val,
        const float* __restrict__ lw1, const float* __restrict__ lb1,
        const float* __restrict__ lw2, const float* __restrict__ lb2,
        const float* __restrict__ lw3, const float* __restrict__ lb3) {
    __shared__ float s_w[8192];                 // 32 KB weight stage
    __shared__ float As[8*68], A2[8*68];        // acts transposed [p][ch]
    __shared__ float Bf[8*132], Cf[8*132];
    int bb = blockIdx.y;
    int pos0 = blockIdx.x * 8;
    int t = threadIdx.x;
    int p = t & 7, oct = t >> 3;                // 32 octs

    for (int i = t*4; i < 4096; i += 1024)
        *(float4*)&s_w[i] = __ldg((const float4*)&spw[i]);
    for (int i = t; i < 512; i += 256) {
        int ci = i >> 3, pp = i & 7;
        As[pp*68 + ci] = __ldg(&g_x4[bb*16384 + ci*256 + pos0 + pp]);
    }
    __syncthreads();
    float vb = __ldg(&val[bb]);

    #pragma unroll
    for (int j = 0; j < 2; j++) {
        int ch = oct*2 + j;
        float acc = __ldg(&spb[ch]) + vb;
        #pragma unroll
        for (int i = 0; i < 64; i += 4) {
            float4 a = *(const float4*)&As[p*68 + i];
            float4 wv = *(const float4*)&s_w[ch*64 + i];
            acc += a.x*wv.x + a.y*wv.y + a.z*wv.z + a.w*wv.w;
        }
        A2[p*68 + ch] = acc;
        g_splat[(bb*64 + ch)*256 + pos0 + p] = acc;
    }
    __syncthreads();

    for (int i = t*4; i < 8192; i += 1024)
        *(float4*)&s_w[i] = __ldg((const float4*)&lw1[i]);
    __syncthreads();
    #pragma unroll
    for (int j = 0; j < 4; j++) {
        int ch = oct*4 + j;
        float acc = __ldg(&lb1[ch]);
        #pragma unroll
        for (int i = 0; i < 64; i += 4) {
            float4 a = *(const float4*)&A2[p*68 + i];
            float4 wv = *(const float4*)&s_w[ch*64 + i];
            acc += a.x*wv.x + a.y*wv.y + a.z*wv.z + a.w*wv.w;
        }
        Bf[p*132 + ch] = fmaxf(acc, 0.f);
    }
    __syncthreads();

    for (int half = 0; half < 2; half++) {
        for (int i = t*4; i < 8192; i += 1024)
            *(float4*)&s_w[i] = __ldg((const float4*)&lw2[half*8192 + i]);
        __syncthreads();
        if ((oct >> 4) == half) {
            int octl = oct & 15;
            #pragma unroll
            for (int j = 0; j < 4; j++) {
                int ch = half*64 + octl*4 + j;
                float acc = __ldg(&lb2[ch]);
                #pragma unroll
                for (int i = 0; i < 128; i += 4) {
                    float4 a = *(const float4*)&Bf[p*132 + i];
                    float4 wv = *(const float4*)&s_w[(octl*4 + j)*128 + i];
                    acc += a.x*wv.x + a.y*wv.y + a.z*wv.z + a.w*wv.w;
                }
                Cf[p*132 + ch] = fmaxf(acc, 0.f);
            }
        }
        __syncthreads();
    }

    for (int i = t*4; i < 8192; i += 1024)
        *(float4*)&s_w[i] = __ldg((const float4*)&lw3[i]);
    __syncthreads();
    #pragma unroll
    for (int j = 0; j < 2; j++) {
        int ch = oct*2 + j;
        float acc = __ldg(&lb3[ch]);
        #pragma unroll
        for (int i = 0; i < 128; i += 4) {
            float4 a = *(const float4*)&Cf[p*132 + i];
            float4 wv = *(const float4*)&s_w[ch*128 + i];
            acc += a.x*wv.x + a.y*wv.y + a.z*wv.z + a.w*wv.w;
        }
        g_l3[(bb*64 + ch)*256 + pos0 + p] = fmaxf(acc, 0.f);
    }
}

// ============== global path ===================================================
__global__ void __launch_bounds__(256) k_global(
        const float* __restrict__ cw,  const float* __restrict__ cb,
        const float* __restrict__ fw1, const float* __restrict__ fb1,
        const float* __restrict__ fw2, const float* __restrict__ fb2) {
    __shared__ float c4[4*64], cp[64], f1[64];
    int bb = blockIdx.x;
    int t = threadIdx.x;
    const float* sp = g_splat + bb*64*256;
    int oc = t >> 6, idx = t & 63;
    int gy2 = idx >> 3, gx2 = idx & 7;
    int pos = (2*gy2)*16 + 2*gx2;
    float acc = cb[oc];
    for (int i = 0; i < 64; i++) acc = fmaf(cw[oc*64+i], sp[i*256+pos], acc);
    c4[oc*64 + idx] = fmaxf(acc, 0.f);
    __syncthreads();
    if (t < 64) {
        int oc2 = t >> 4, py = (t >> 2) & 3, px = t & 3;
        cp[t] = 0.25f*(c4[oc2*64 + (2*py)*8 + 2*px]   + c4[oc2*64 + (2*py)*8 + 2*px+1] +
                       c4[oc2*64 + (2*py+1)*8 + 2*px] + c4[oc2*64 + (2*py+1)*8 + 2*px+1]);
    }
    __syncthreads();
    if (t < 64) {
        float a2 = fb1[t];
        for (int i = 0; i < 64; i++) a2 = fmaf(fw1[t*64+i], cp[i], a2);
        f1[t] = fmaxf(a2, 0.f);
    }
    __syncthreads();
    if (t < 64) {
        float a2 = fb2[t];
        for (int i = 0; i < 64; i++) a2 = fmaf(fw2[t*64+i], f1[i], a2);
        g_cvec[bb*64 + t] = fmaxf(a2, 0.f);
    }
}

// ============== coeff: fused=relu(c+loc); pw 64->96; write grid ==============
__global__ void __launch_bounds__(256) k_coeff(const float* __restrict__ gw,
                                               const float* __restrict__ gb) {
    __shared__ float s_gw[6144];
    __shared__ float fused[16*68];              // [p][ch]
    int tl = blockIdx.x;
    int bb = blockIdx.y;
    int t = threadIdx.x;
    for (int i = t*4; i < 6144; i += 1024)
        *(float4*)&s_gw[i] = __ldg((const float4*)&gw[i]);
    const float* l3p = g_l3 + bb*64*256;
    const float* cv = g_cvec + bb*64;
    for (int o = t; o < 1024; o += 256) {
        int ch = o >> 4, p = o & 15;
        fused[p*68 + ch] = fmaxf(cv[ch] + l3p[ch*256 + tl*16 + p], 0.f);
    }
    __syncthreads();
    for (int o = t; o < 1536; o += 256) {
        int och = o >> 4, p = o & 15;
        float acc = __ldg(&gb[och]);
        #pragma unroll
        for (int i = 0; i < 64; i += 4) {
            float4 a = *(const float4*)&fused[p*68 + i];
            float4 wv = *(const float4*)&s_gw[och*64 + i];
            acc += a.x*wv.x + a.y*wv.y + a.z*wv.z + a.w*wv.w;
        }
        int lb = och / 12, cc = och % 12;
        g_grid[((bb*12 + cc)*8 + lb)*256 + tl*16 + p] = acc;
    }
}

// ============== fused guide + bilateral slice =================================
__global__ void __launch_bounds__(256) k_slice(
        const float* __restrict__ im,
        const float* __restrict__ ccm_w, const float* __restrict__ ccm_b,
        const float* __restrict__ shifts, const float* __restrict__ slopes,
        const float* __restrict__ prw, const float* __restrict__ prb,
        float* __restrict__ out) {
    int bx = blockIdx.x, by = blockIdx.y, bb = blockIdx.z;
    __shared__ float sg[864];               // [cell(j*3+k)][z][c12]
    __shared__ float gy[2][4*72*4];         // double-buffered y-interp tables
    __shared__ float s_ccm[9], s_ccmb[3], s_prw[3], s_prb[1];
    __shared__ float s_sh[48];
    __shared__ float s_cs[3][17], s_csh[3][17];
    int t = threadIdx.x;

    const float* gr = g_grid + (size_t)bb * 12 * 8 * 256;
    for (int k = t; k < 864; k += 256) {
        int c = k % 12;
        int z = (k / 12) % 8;
        int cell = k / 96;
        int j = cell / 3, kx = cell % 3;
        int yi = min(max(by - 1 + j, 0), 15);
        int xi = min(max(bx - 1 + kx, 0), 15);
        sg[k] = gr[(c*8 + z)*256 + yi*16 + xi];
    }
    if (t < 9)               s_ccm[t] = ccm_w[t];
    if (t >= 16 && t < 19)   s_ccmb[t-16] = ccm_b[t-16];
    if (t >= 32 && t < 80)   s_sh[t-32] = shifts[t-32];
    if (t >= 96 && t < 99)   s_prw[t-96] = prw[t-96];
    if (t == 102)            s_prb[0] = prb[0];
    if (t >= 104 && t < 107) {
        int c = t - 104;
        float cs = 0.f, csh = 0.f;
        s_cs[c][0] = 0.f; s_csh[c][0] = 0.f;
        #pragma unroll
        for (int k = 0; k < 16; k++) {
            float s = slopes[c*16+k], h = shifts[c*16+k];
            cs += s; csh += s*h;
            s_cs[c][k+1] = cs; s_csh[c][k+1] = csh;
        }
    }
    __syncthreads();

    int g = t >> 6;
    int lx = t & 63;
    int x = bx*64 + lx;
    float cxv = ((float)x + 0.5f) * (1.0f/64.0f) - 0.5f;
    float wx = cxv - floorf(cxv);
    int k0 = (int)floorf(cxv) - (bx - 1);
    const float* imb = im + (size_t)bb * 3 * 1048576;
    float* outb = out + (size_t)bb * 3 * 1048576;

    for (int r = 0; r < 16; r++) {
        int buf = r & 1;
        int y = by*64 + g + 4*r;
        float cyv = ((float)y + 0.5f) * (1.0f/64.0f) - 0.5f;
        float wy = cyv - floorf(cyv);
        int j0 = (int)floorf(cyv) - (by - 1);

        for (int e = lx; e < 72; e += 64) {
            int cellx = e / 24;
            int z = (e / 3) % 8;
            int v = e % 3;
            float4 a = ((const float4*)sg)[((j0*3 + cellx)*8 + z)*3 + v];
            float4 b4 = ((const float4*)sg)[(((j0+1)*3 + cellx)*8 + z)*3 + v];
            float4 res;
            res.x = fmaf(wy, b4.x - a.x, a.x);
            res.y = fmaf(wy, b4.y - a.y, a.y);
            res.z = fmaf(wy, b4.z - a.z, a.z);
            res.w = fmaf(wy, b4.w - a.w, a.w);
            ((float4*)gy[buf])[g*72 + e] = res;
        }
        asm volatile("bar.sync %0, %1;" :: "r"(g+1), "r"(64) : "memory");

        size_t poff = (size_t)y * 1024 + x;
        float i0 = __ldg(&imb[poff]);
        float i1 = __ldg(&imb[poff + 1048576]);
        float i2 = __ldg(&imb[poff + 2097152]);

        float q0 = s_ccmb[0] + s_ccm[0]*i0 + s_ccm[1]*i1 + s_ccm[2]*i2;
        float q1 = s_ccmb[1] + s_ccm[3]*i0 + s_ccm[4]*i1 + s_ccm[5]*i2;
        float q2 = s_ccmb[2] + s_ccm[6]*i0 + s_ccm[7]*i1 + s_ccm[8]*i2;
        float tt[3];
        float qv[3] = {q0, q1, q2};
        #pragma unroll
        for (int c = 0; c < 3; c++) {
            const float* H = &s_sh[c*16];
            float gv = qv[c];
            int p = (gv > H[7]) ? 8 : 0;
            p += (gv > H[p+3]) ? 4 : 0;
            p += (gv > H[p+1]) ? 2 : 0;
            p += (gv > H[p])   ? 1 : 0;
            p += (gv > H[p])   ? 1 : 0;
            tt[c] = fmaf(gv, s_cs[c][p], -s_csh[c][p]);
        }
        float gg = s_prb[0] + s_prw[0]*tt[0] + s_prw[1]*tt[1] + s_prw[2]*tt[2];
        float guide = fminf(fmaxf(gg, 0.f), 1.f);

        float cz = guide * 8.0f - 0.5f;
        float z0f = floorf(cz);
        float wz = cz - z0f;
        int z0 = (int)z0f;
        int zi0 = min(max(z0, 0), 7);
        int zi1 = min(max(z0 + 1, 0), 7);

        float w00 = (1.f-wx)*(1.f-wz), w01 = (1.f-wx)*wz;
        float w10 = wx*(1.f-wz),       w11 = wx*wz;

        const float4* T = (const float4*)gy[buf];
        int bA = (g*3 + k0)*8;
        int bB = bA + 8;
        int iA0 = (bA + zi0)*3, iA1 = (bA + zi1)*3;
        int iB0 = (bB + zi0)*3, iB1 = (bB + zi1)*3;

        float a0,a1,a2,a3,a4,a5,a6,a7,a8,a9,a10,a11;
        {
            float4 v0 = T[iA0], v1 = T[iA1], v2 = T[iB0], v3 = T[iB1];
            a0 = w00*v0.x + w01*v1.x + w10*v2.x + w11*v3.x;
            a1 = w00*v0.y + w01*v1.y + w10*v2.y + w11*v3.y;
            a2 = w00*v0.z + w01*v1.z + w10*v2.z + w11*v3.z;
            a3 = w00*v0.w + w01*v1.w + w10*v2.w + w11*v3.w;
        }
        {
            float4 v0 = T[iA0+1], v1 = T[iA1+1], v2 = T[iB0+1], v3 = T[iB1+1];
            a4 = w00*v0.x + w01*v1.x + w10*v2.x + w11*v3.x;
            a5 = w00*v0.y + w01*v1.y + w10*v2.y + w11*v3.y;
            a6 = w00*v0.z + w01*v1.z + w10*v2.z + w11*v3.z;
            a7 = w00*v0.w + w01*v1.w + w10*v2.w + w11*v3.w;
        }
        {
            float4 v0 = T[iA0+2], v1 = T[iA1+2], v2 = T[iB0+2], v3 = T[iB1+2];
            a8  = w00*v0.x + w01*v1.x + w10*v2.x + w11*v3.x;
            a9  = w00*v0.y + w01*v1.y + w10*v2.y + w11*v3.y;
            a10 = w00*v0.z + w01*v1.z + w10*v2.z + w11*v3.z;
            a11 = w00*v0.w + w01*v1.w + w10*v2.w + w11*v3.w;
        }
        outb[poff]           = fmaf(a0, i0, fmaf(a1, i1, fmaf(a2,  i2, a3)));
        outb[poff + 1048576] = fmaf(a4, i0, fmaf(a5, i1, fmaf(a6,  i2, a7)));
        outb[poff + 2097152] = fmaf(a8, i0, fmaf(a9, i1, fmaf(a10, i2, a11)));
    }
}

// ---------------- launcher ---------------------------------------------------
extern "C" void kernel_launch(void* const* d_in, const int* in_sizes, int n_in,
                              void* d_out, int out_size) {
    const float* image = (const float*)d_in[0];
    const float* val   = (const float*)d_in[1];
    const float* sw0 = (const float*)d_in[2];  const float* sb0 = (const float*)d_in[3];
    const float* sw1 = (const float*)d_in[4];  const float* sb1 = (const float*)d_in[5];
    const float* sw2 = (const float*)d_in[6];  const float* sb2 = (const float*)d_in[7];
    const float* sw3 = (const float*)d_in[8];  const float* sb3 = (const float*)d_in[9];
    const float* spw = (const float*)d_in[10]; const float* spb = (const float*)d_in[11];
    const float* lw1 = (const float*)d_in[12]; const float* lb1 = (const float*)d_in[13];
    const float* lw2 = (const float*)d_in[14]; const float* lb2 = (const float*)d_in[15];
    const float* lw3 = (const float*)d_in[16]; const float* lb3 = (const float*)d_in[17];
    const float* cw  = (const float*)d_in[18]; const float* cb  = (const float*)d_in[19];
    const float* fw1 = (const float*)d_in[20]; const float* fb1 = (const float*)d_in[21];
    const float* fw2 = (const float*)d_in[22]; const float* fb2 = (const float*)d_in[23];
    const float* gw  = (const float*)d_in[24]; const float* gb  = (const float*)d_in[25];
    const float* ccm_w = (const float*)d_in[26]; const float* ccm_b = (const float*)d_in[27];
    const float* shifts = (const float*)d_in[28];
    const float* slopes = (const float*)d_in[29];
    const float* prw = (const float*)d_in[30]; const float* prb = (const float*)d_in[31];
    float* out = (float*)d_out;

    k_prep<<<24, 256>>>(sw1, sw2, sw3);
    k_conv1<<<dim3(256, 4), 256>>>(image, sw0, sb0);
    k_conv2<<<dim3(64, 1, 4), 256>>>(sb1);
    k_conv3<<<dim3(16, 2, 4), 256>>>(sb2);
    k_conv4<<<dim3(16, 4, 4), 128>>>(sb3);
    k_mid<<<dim3(32, 4), 256>>>(spw, spb, val, lw1, lb1, lw2, lb2, lw3, lb3);
    k_global<<<4, 256>>>(cw, cb, fw1, fb1, fw2, fb2);
    k_coeff<<<dim3(16, 4), 256>>>(gw, gb);
    k_slice<<<dim3(16, 16, 4), 256>>>(image, ccm_w, ccm_b, shifts, slopes, prw, prb, out);
}

// round 9
// speedup vs baseline: 1.5223x; 1.0051x over previous
#include <cuda_runtime.h>

// ---------------- scratch (device globals; no runtime alloc) ----------------
__device__ float g_x1[4*8*128*128];
__device__ float g_x2[4*16*64*64];
__device__ float g_x3[4*32*32*32];
__device__ float g_x4[4*64*16*16];
__device__ float g_splat[4*64*256];
__device__ float g_l3[4*64*256];
__device__ float g_cvec[4*64];
__device__ float g_grid[4*12*8*256];   // [b][cc 12][lb 8][y 16][x 16]
// padded transposed conv weights: [cog][coq][ CO_PER*9*CI + 4 ]
__device__ float g_w2T[2*4*148];       // conv2: COG=8 NCOQ=4 CO_PER=2 CI=8
__device__ float g_w3T[4*4*292];       // conv3: COG=8 NCOQ=4 CO_PER=2 CI=16
__device__ float g_w4T[2*16*580];      // conv4: COG=32 NCOQ=16 CO_PER=2 CI=32

// ============== prep: transpose+pad conv weights =============================
// dst offset = cog*NCOQ*WSTR + coq*WSTR + (j*9 + kk)*CI + ci
template<int CI, int COG, int NCOQ, int NCO>
__device__ __forceinline__ void prep_one(const float* __restrict__ w,
                                         float* __restrict__ dst,
                                         int t, int stride) {
    constexpr int CO_PER = COG/NCOQ;
    constexpr int WSTR = CO_PER*9*CI + 4;
    for (int idx = t; idx < NCO*CI*9; idx += stride) {
        int co = idx / (CI*9);
        int rem = idx % (CI*9);
        int ci = rem / 9, kk = rem % 9;
        int cog = co / COG, coL = co % COG;
        int coq = coL / CO_PER, j = coL % CO_PER;
        dst[(cog*NCOQ + coq)*WSTR + (j*9 + kk)*CI + ci] = __ldg(&w[idx]);
    }
}
__global__ void k_prep(const float* __restrict__ w2, const float* __restrict__ w3,
                       const float* __restrict__ w4) {
    int t = blockIdx.x*256 + threadIdx.x;
    int stride = gridDim.x*256;
    prep_one<8, 8, 4, 16>(w2, g_w2T, t, stride);
    prep_one<16, 8, 4, 32>(w3, g_w3T, t, stride);
    prep_one<32, 32, 16, 64>(w4, g_w4T, t, stride);
}

// ============== generic 3x3 stride-2 conv =====================================
// lanes: coq in low bits (input broadcast, weight banks spread via WSTR pad)
template<int CI, int COG, int NCOQ, int CO_TOTAL, int IHW, int OHW, int TILE,
         int THREADS>
__device__ __forceinline__ void conv_run(const float* __restrict__ in,
        const float* __restrict__ wT, const float* __restrict__ bias,
        float* __restrict__ out, float* __restrict__ s_in, float* __restrict__ s_w,
        int bb, int tile, int cog) {
    constexpr int IT  = 2*TILE+1;
    constexpr int NT  = OHW/TILE;
    constexpr int CIP = CI + 4;
    constexpr int CO_PER = COG/NCOQ;
    constexpr int WSTR = CO_PER*9*CI + 4;
    constexpr int NWP = NCOQ*WSTR;
    int ty0 = (tile/NT)*TILE, tx0 = (tile%NT)*TILE;
    int t = threadIdx.x;

    // weights: straight coalesced float4 copy (pre-transposed + padded)
    const float* wg = wT + (size_t)cog*NWP;
    #pragma unroll
    for (int i = t*4; i < NWP; i += THREADS*4)
        *(float4*)&s_w[i] = __ldg((const float4*)&wg[i]);
    // input tile -> smem [i][ci]
    const float* inb = in + (size_t)bb*CI*IHW*IHW;
    #pragma unroll
    for (int k = t; k < IT*IT*CI; k += THREADS) {
        int ci = k / (IT*IT);
        int i  = k % (IT*IT);
        int iy = 2*ty0 - 1 + i/IT;
        int ix = 2*tx0 - 1 + i%IT;
        float v = 0.f;
        if (iy >= 0 && iy < IHW && ix >= 0 && ix < IHW)
            v = __ldg(&inb[(size_t)ci*IHW*IHW + (size_t)iy*IHW + ix]);
        s_in[i*CIP + ci] = v;
    }
    __syncthreads();

    int coq = t & (NCOQ-1);
    int pos = t / NCOQ;
    int py = pos / TILE, px = pos % TILE;
    float acc[CO_PER];
    #pragma unroll
    for (int j = 0; j < CO_PER; j++) acc[j] = bias[cog*COG + coq*CO_PER + j];

    #pragma unroll
    for (int c0 = 0; c0 < CI; c0 += 4) {
        #pragma unroll
        for (int ky = 0; ky < 3; ky++) {
            const float* rp = s_in + ((2*py+ky)*IT + 2*px)*CIP + c0;
            float4 i0 = *(const float4*)(rp);
            float4 i1 = *(const float4*)(rp + CIP);
            float4 i2 = *(const float4*)(rp + 2*CIP);
            #pragma unroll
            for (int j = 0; j < CO_PER; j++) {
                const float* wb = s_w + coq*WSTR + (j*9 + ky*3)*CI + c0;
                float4 w0 = *(const float4*)(wb);
                float4 w1 = *(const float4*)(wb + CI);
                float4 w2 = *(const float4*)(wb + 2*CI);
                acc[j] += i0.x*w0.x + i0.y*w0.y + i0.z*w0.z + i0.w*w0.w
                        + i1.x*w1.x + i1.y*w1.y + i1.z*w1.z + i1.w*w1.w
                        + i2.x*w2.x + i2.y*w2.y + i2.z*w2.z + i2.w*w2.w;
            }
        }
    }
    #pragma unroll
    for (int j = 0; j < CO_PER; j++) {
        int co = cog*COG + coq*CO_PER + j;
        out[(size_t)(bb*CO_TOTAL + co)*OHW*OHW + (size_t)(ty0+py)*OHW + tx0+px]
            = fmaxf(acc[j], 0.f);
    }
}

// ============== conv1: fused bilinear downsample + 3x3 s2 conv ================
__global__ void __launch_bounds__(256) k_conv1(const float* __restrict__ im,
        const float* __restrict__ w, const float* __restrict__ bias) {
    constexpr int TILE = 8, IT = 17, NT = 16;
    constexpr int TPC = 32, OPT = 2;
    __shared__ float s_in[IT*IT*4];
    __shared__ float s_w[8*3*9];
    int bb = blockIdx.y;
    int tile = blockIdx.x;
    int ty0 = (tile/NT)*TILE, tx0 = (tile%NT)*TILE;
    int t = threadIdx.x;
    if (t < 216) s_w[t] = __ldg(&w[t]);
    const float* imb = im + (size_t)bb * 3 * 1048576;
    #pragma unroll
    for (int k = t; k < 289*3; k += 256) {
        int ci = k / 289, i = k % 289;
        int iy = 2*ty0 - 1 + i/IT;
        int ix = 2*tx0 - 1 + i%IT;
        float v = 0.f;
        if (iy >= 0 && iy < 256 && ix >= 0 && ix < 256) {
            const float4* p = (const float4*)(imb + (size_t)ci*1048576 + (size_t)(4*iy+1)*1024) + ix;
            float4 r1 = __ldg(p);
            float4 r2 = __ldg(p + 256);
            v = 0.25f*(r1.y + r1.z + r2.y + r2.z);
        }
        s_in[i*4 + ci] = v;
    }
    __syncthreads();
    int co = t / TPC;
    int pbase = t % TPC;
    float acc[OPT];
    #pragma unroll
    for (int k = 0; k < OPT; k++) acc[k] = bias[co];
    const float* wc = s_w + co*27;
    float4 wk[9];
    #pragma unroll
    for (int k = 0; k < 9; k++) {
        wk[k].x = wc[k]; wk[k].y = wc[9+k]; wk[k].z = wc[18+k]; wk[k].w = 0.f;
    }
    #pragma unroll
    for (int k = 0; k < OPT; k++) {
        int p = pbase + k*TPC;
        int py = p/TILE, px = p%TILE;
        #pragma unroll
        for (int ky = 0; ky < 3; ky++)
        #pragma unroll
        for (int kx = 0; kx < 3; kx++) {
            float4 v = *(const float4*)&s_in[((2*py+ky)*IT + 2*px+kx)*4];
            float4 wv = wk[ky*3+kx];
            acc[k] += v.x*wv.x + v.y*wv.y + v.z*wv.z;
        }
    }
    float* outb = g_x1 + (size_t)bb*8*128*128;
    #pragma unroll
    for (int k = 0; k < OPT; k++) {
        int p = pbase + k*TPC;
        outb[(size_t)co*16384 + (size_t)(ty0+p/TILE)*128 + tx0 + p%TILE] = fmaxf(acc[k], 0.f);
    }
}

// ============== conv2..4 =====================================================
__global__ void __launch_bounds__(256) k_conv2(const float* __restrict__ b) {
    __shared__ float s_in[289*12];
    __shared__ float s_w[4*148];
    conv_run<8, 8, 4, 16, 128, 64, 8, 256>(g_x1, g_w2T, b, g_x2, s_in, s_w,
                                           blockIdx.z, blockIdx.x, blockIdx.y);
}
__global__ void __launch_bounds__(256) k_conv3(const float* __restrict__ b) {
    __shared__ float s_in[289*20];
    __shared__ float s_w[4*292];
    conv_run<16, 8, 4, 32, 64, 32, 8, 256>(g_x2, g_w3T, b, g_x3, s_in, s_w,
                                           blockIdx.z, blockIdx.x, blockIdx.y);
}
__global__ void __launch_bounds__(256) k_conv4(const float* __restrict__ b) {
    __shared__ float s_in[81*36];
    __shared__ float s_w[16*580];
    conv_run<32, 32, 16, 64, 32, 16, 4, 256>(g_x3, g_w4T, b, g_x4, s_in, s_w,
                                             blockIdx.z, blockIdx.x, blockIdx.y);
}

// ============== mid: splat + local MLP, 8 positions/block, smem weights ======
__global__ void __launch_bounds__(256) k_mid(
        const float* __restrict__ spw, const float* __restrict__ spb,
        const float* __restrict__ val,
        const float* __restrict__ lw1, const float* __restrict__ lb1,
        const float* __restrict__ lw2, const float* __restrict__ lb2,
        const float* __restrict__ lw3, const float* __restrict__ lb3) {
    __shared__ float s_w[8192];                 // 32 KB weight stage
    __shared__ float As[8*68], A2[8*68];        // acts transposed [p][ch]
    __shared__ float Bf[8*132], Cf[8*132];
    int bb = blockIdx.y;
    int pos0 = blockIdx.x * 8;
    int t = threadIdx.x;
    int p = t & 7, oct = t >> 3;                // 32 octs

    for (int i = t*4; i < 4096; i += 1024)
        *(float4*)&s_w[i] = __ldg((const float4*)&spw[i]);
    for (int i = t; i < 512; i += 256) {
        int ci = i >> 3, pp = i & 7;
        As[pp*68 + ci] = __ldg(&g_x4[bb*16384 + ci*256 + pos0 + pp]);
    }
    __syncthreads();
    float vb = __ldg(&val[bb]);

    #pragma unroll
    for (int j = 0; j < 2; j++) {
        int ch = oct*2 + j;
        float acc = __ldg(&spb[ch]) + vb;
        #pragma unroll
        for (int i = 0; i < 64; i += 4) {
            float4 a = *(const float4*)&As[p*68 + i];
            float4 wv = *(const float4*)&s_w[ch*64 + i];
            acc += a.x*wv.x + a.y*wv.y + a.z*wv.z + a.w*wv.w;
        }
        A2[p*68 + ch] = acc;
        g_splat[(bb*64 + ch)*256 + pos0 + p] = acc;
    }
    __syncthreads();

    for (int i = t*4; i < 8192; i += 1024)
        *(float4*)&s_w[i] = __ldg((const float4*)&lw1[i]);
    __syncthreads();
    #pragma unroll
    for (int j = 0; j < 4; j++) {
        int ch = oct*4 + j;
        float acc = __ldg(&lb1[ch]);
        #pragma unroll
        for (int i = 0; i < 64; i += 4) {
            float4 a = *(const float4*)&A2[p*68 + i];
            float4 wv = *(const float4*)&s_w[ch*64 + i];
            acc += a.x*wv.x + a.y*wv.y + a.z*wv.z + a.w*wv.w;
        }
        Bf[p*132 + ch] = fmaxf(acc, 0.f);
    }
    __syncthreads();

    for (int half = 0; half < 2; half++) {
        for (int i = t*4; i < 8192; i += 1024)
            *(float4*)&s_w[i] = __ldg((const float4*)&lw2[half*8192 + i]);
        __syncthreads();
        if ((oct >> 4) == half) {
            int octl = oct & 15;
            #pragma unroll
            for (int j = 0; j < 4; j++) {
                int ch = half*64 + octl*4 + j;
                float acc = __ldg(&lb2[ch]);
                #pragma unroll
                for (int i = 0; i < 128; i += 4) {
                    float4 a = *(const float4*)&Bf[p*132 + i];
                    float4 wv = *(const float4*)&s_w[(octl*4 + j)*128 + i];
                    acc += a.x*wv.x + a.y*wv.y + a.z*wv.z + a.w*wv.w;
                }
                Cf[p*132 + ch] = fmaxf(acc, 0.f);
            }
        }
        __syncthreads();
    }

    for (int i = t*4; i < 8192; i += 1024)
        *(float4*)&s_w[i] = __ldg((const float4*)&lw3[i]);
    __syncthreads();
    #pragma unroll
    for (int j = 0; j < 2; j++) {
        int ch = oct*2 + j;
        float acc = __ldg(&lb3[ch]);
        #pragma unroll
        for (int i = 0; i < 128; i += 4) {
            float4 a = *(const float4*)&Cf[p*132 + i];
            float4 wv = *(const float4*)&s_w[ch*128 + i];
            acc += a.x*wv.x + a.y*wv.y + a.z*wv.z + a.w*wv.w;
        }
        g_l3[(bb*64 + ch)*256 + pos0 + p] = fmaxf(acc, 0.f);
    }
}

// ============== global path ===================================================
__global__ void __launch_bounds__(256) k_global(
        const float* __restrict__ cw,  const float* __restrict__ cb,
        const float* __restrict__ fw1, const float* __restrict__ fb1,
        const float* __restrict__ fw2, const float* __restrict__ fb2) {
    __shared__ float c4[4*64], cp[64], f1[64];
    int bb = blockIdx.x;
    int t = threadIdx.x;
    const float* sp = g_splat + bb*64*256;
    int oc = t >> 6, idx = t & 63;
    int gy2 = idx >> 3, gx2 = idx & 7;
    int pos = (2*gy2)*16 + 2*gx2;
    float acc = cb[oc];
    for (int i = 0; i < 64; i++) acc = fmaf(cw[oc*64+i], sp[i*256+pos], acc);
    c4[oc*64 + idx] = fmaxf(acc, 0.f);
    __syncthreads();
    if (t < 64) {
        int oc2 = t >> 4, py = (t >> 2) & 3, px = t & 3;
        cp[t] = 0.25f*(c4[oc2*64 + (2*py)*8 + 2*px]   + c4[oc2*64 + (2*py)*8 + 2*px+1] +
                       c4[oc2*64 + (2*py+1)*8 + 2*px] + c4[oc2*64 + (2*py+1)*8 + 2*px+1]);
    }
    __syncthreads();
    if (t < 64) {
        float a2 = fb1[t];
        for (int i = 0; i < 64; i++) a2 = fmaf(fw1[t*64+i], cp[i], a2);
        f1[t] = fmaxf(a2, 0.f);
    }
    __syncthreads();
    if (t < 64) {
        float a2 = fb2[t];
        for (int i = 0; i < 64; i++) a2 = fmaf(fw2[t*64+i], f1[i], a2);
        g_cvec[bb*64 + t] = fmaxf(a2, 0.f);
    }
}

// ============== coeff: fused=relu(c+loc); pw 64->96; write grid ==============
__global__ void __launch_bounds__(256) k_coeff(const float* __restrict__ gw,
                                               const float* __restrict__ gb) {
    __shared__ float s_gw[6144];
    __shared__ float fused[16*68];              // [p][ch]
    int tl = blockIdx.x;
    int bb = blockIdx.y;
    int t = threadIdx.x;
    for (int i = t*4; i < 6144; i += 1024)
        *(float4*)&s_gw[i] = __ldg((const float4*)&gw[i]);
    const float* l3p = g_l3 + bb*64*256;
    const float* cv = g_cvec + bb*64;
    for (int o = t; o < 1024; o += 256) {
        int ch = o >> 4, p = o & 15;
        fused[p*68 + ch] = fmaxf(cv[ch] + l3p[ch*256 + tl*16 + p], 0.f);
    }
    __syncthreads();
    for (int o = t; o < 1536; o += 256) {
        int och = o >> 4, p = o & 15;
        float acc = __ldg(&gb[och]);
        #pragma unroll
        for (int i = 0; i < 64; i += 4) {
            float4 a = *(const float4*)&fused[p*68 + i];
            float4 wv = *(const float4*)&s_gw[och*64 + i];
            acc += a.x*wv.x + a.y*wv.y + a.z*wv.z + a.w*wv.w;
        }
        int lb = och / 12, cc = och % 12;
        g_grid[((bb*12 + cc)*8 + lb)*256 + tl*16 + p] = acc;
    }
}

// ============== fused guide + bilateral slice =================================
__global__ void __launch_bounds__(256) k_slice(
        const float* __restrict__ im,
        const float* __restrict__ ccm_w, const float* __restrict__ ccm_b,
        const float* __restrict__ shifts, const float* __restrict__ slopes,
        const float* __restrict__ prw, const float* __restrict__ prb,
        float* __restrict__ out) {
    int bx = blockIdx.x, by = blockIdx.y, bb = blockIdx.z;
    __shared__ float sg[864];               // [cell(j*3+k)][z][c12]
    __shared__ float gy[2][4*72*4];         // double-buffered y-interp tables
    __shared__ float s_ccm[9], s_ccmb[3], s_prw[3], s_prb[1];
    __shared__ float s_sh[48];
    __shared__ float s_cs[3][17], s_csh[3][17];
    int t = threadIdx.x;

    const float* gr = g_grid + (size_t)bb * 12 * 8 * 256;
    for (int k = t; k < 864; k += 256) {
        int c = k % 12;
        int z = (k / 12) % 8;
        int cell = k / 96;
        int j = cell / 3, kx = cell % 3;
        int yi = min(max(by - 1 + j, 0), 15);
        int xi = min(max(bx - 1 + kx, 0), 15);
        sg[k] = gr[(c*8 + z)*256 + yi*16 + xi];
    }
    if (t < 9)               s_ccm[t] = ccm_w[t];
    if (t >= 16 && t < 19)   s_ccmb[t-16] = ccm_b[t-16];
    if (t >= 32 && t < 80)   s_sh[t-32] = shifts[t-32];
    if (t >= 96 && t < 99)   s_prw[t-96] = prw[t-96];
    if (t == 102)            s_prb[0] = prb[0];
    if (t >= 104 && t < 107) {
        int c = t - 104;
        float cs = 0.f, csh = 0.f;
        s_cs[c][0] = 0.f; s_csh[c][0] = 0.f;
        #pragma unroll
        for (int k = 0; k < 16; k++) {
            float s = slopes[c*16+k], h = shifts[c*16+k];
            cs += s; csh += s*h;
            s_cs[c][k+1] = cs; s_csh[c][k+1] = csh;
        }
    }
    __syncthreads();

    int g = t >> 6;
    int lx = t & 63;
    int x = bx*64 + lx;
    float cxv = ((float)x + 0.5f) * (1.0f/64.0f) - 0.5f;
    float wx = cxv - floorf(cxv);
    int k0 = (int)floorf(cxv) - (bx - 1);
    const float* imb = im + (size_t)bb * 3 * 1048576;
    float* outb = out + (size_t)bb * 3 * 1048576;

    for (int r = 0; r < 16; r++) {
        int buf = r & 1;
        int y = by*64 + g + 4*r;
        float cyv = ((float)y + 0.5f) * (1.0f/64.0f) - 0.5f;
        float wy = cyv - floorf(cyv);
        int j0 = (int)floorf(cyv) - (by - 1);

        for (int e = lx; e < 72; e += 64) {
            int cellx = e / 24;
            int z = (e / 3) % 8;
            int v = e % 3;
            float4 a = ((const float4*)sg)[((j0*3 + cellx)*8 + z)*3 + v];
            float4 b4 = ((const float4*)sg)[(((j0+1)*3 + cellx)*8 + z)*3 + v];
            float4 res;
            res.x = fmaf(wy, b4.x - a.x, a.x);
            res.y = fmaf(wy, b4.y - a.y, a.y);
            res.z = fmaf(wy, b4.z - a.z, a.z);
            res.w = fmaf(wy, b4.w - a.w, a.w);
            ((float4*)gy[buf])[g*72 + e] = res;
        }
        asm volatile("bar.sync %0, %1;" :: "r"(g+1), "r"(64) : "memory");

        size_t poff = (size_t)y * 1024 + x;
        float i0 = __ldg(&imb[poff]);
        float i1 = __ldg(&imb[poff + 1048576]);
        float i2 = __ldg(&imb[poff + 2097152]);

        float q0 = s_ccmb[0] + s_ccm[0]*i0 + s_ccm[1]*i1 + s_ccm[2]*i2;
        float q1 = s_ccmb[1] + s_ccm[3]*i0 + s_ccm[4]*i1 + s_ccm[5]*i2;
        float q2 = s_ccmb[2] + s_ccm[6]*i0 + s_ccm[7]*i1 + s_ccm[8]*i2;
        float tt[3];
        float qv[3] = {q0, q1, q2};
        #pragma unroll
        for (int c = 0; c < 3; c++) {
            const float* H = &s_sh[c*16];
            float gv = qv[c];
            int p = (gv > H[7]) ? 8 : 0;
            p += (gv > H[p+3]) ? 4 : 0;
            p += (gv > H[p+1]) ? 2 : 0;
            p += (gv > H[p])   ? 1 : 0;
            p += (gv > H[p])   ? 1 : 0;
            tt[c] = fmaf(gv, s_cs[c][p], -s_csh[c][p]);
        }
        float gg = s_prb[0] + s_prw[0]*tt[0] + s_prw[1]*tt[1] + s_prw[2]*tt[2];
        float guide = fminf(fmaxf(gg, 0.f), 1.f);

        float cz = guide * 8.0f - 0.5f;
        float z0f = floorf(cz);
        float wz = cz - z0f;
        int z0 = (int)z0f;
        int zi0 = min(max(z0, 0), 7);
        int zi1 = min(max(z0 + 1, 0), 7);

        float w00 = (1.f-wx)*(1.f-wz), w01 = (1.f-wx)*wz;
        float w10 = wx*(1.f-wz),       w11 = wx*wz;

        const float4* T = (const float4*)gy[buf];
        int bA = (g*3 + k0)*8;
        int bB = bA + 8;
        int iA0 = (bA + zi0)*3, iA1 = (bA + zi1)*3;
        int iB0 = (bB + zi0)*3, iB1 = (bB + zi1)*3;

        float a0,a1,a2,a3,a4,a5,a6,a7,a8,a9,a10,a11;
        {
            float4 v0 = T[iA0], v1 = T[iA1], v2 = T[iB0], v3 = T[iB1];
            a0 = w00*v0.x + w01*v1.x + w10*v2.x + w11*v3.x;
            a1 = w00*v0.y + w01*v1.y + w10*v2.y + w11*v3.y;
            a2 = w00*v0.z + w01*v1.z + w10*v2.z + w11*v3.z;
            a3 = w00*v0.w + w01*v1.w + w10*v2.w + w11*v3.w;
        }
        {
            float4 v0 = T[iA0+1], v1 = T[iA1+1], v2 = T[iB0+1], v3 = T[iB1+1];
            a4 = w00*v0.x + w01*v1.x + w10*v2.x + w11*v3.x;
            a5 = w00*v0.y + w01*v1.y + w10*v2.y + w11*v3.y;
            a6 = w00*v0.z + w01*v1.z + w10*v2.z + w11*v3.z;
            a7 = w00*v0.w + w01*v1.w + w10*v2.w + w11*v3.w;
        }
        {
            float4 v0 = T[iA0+2], v1 = T[iA1+2], v2 = T[iB0+2], v3 = T[iB1+2];
            a8  = w00*v0.x + w01*v1.x + w10*v2.x + w11*v3.x;
            a9  = w00*v0.y + w01*v1.y + w10*v2.y + w11*v3.y;
            a10 = w00*v0.z + w01*v1.z + w10*v2.z + w11*v3.z;
            a11 = w00*v0.w + w01*v1.w + w10*v2.w + w11*v3.w;
        }
        outb[poff]           = fmaf(a0, i0, fmaf(a1, i1, fmaf(a2,  i2, a3)));
        outb[poff + 1048576] = fmaf(a4, i0, fmaf(a5, i1, fmaf(a6,  i2, a7)));
        outb[poff + 2097152] = fmaf(a8, i0, fmaf(a9, i1, fmaf(a10, i2, a11)));
    }
}

// ---------------- launcher ---------------------------------------------------
extern "C" void kernel_launch(void* const* d_in, const int* in_sizes, int n_in,
                              void* d_out, int out_size) {
    const float* image = (const float*)d_in[0];
    const float* val   = (const float*)d_in[1];
    const float* sw0 = (const float*)d_in[2];  const float* sb0 = (const float*)d_in[3];
    const float* sw1 = (const float*)d_in[4];  const float* sb1 = (const float*)d_in[5];
    const float* sw2 = (const float*)d_in[6];  const float* sb2 = (const float*)d_in[7];
    const float* sw3 = (const float*)d_in[8];  const float* sb3 = (const float*)d_in[9];
    const float* spw = (const float*)d_in[10]; const float* spb = (const float*)d_in[11];
    const float* lw1 = (const float*)d_in[12]; const float* lb1 = (const float*)d_in[13];
    const float* lw2 = (const float*)d_in[14]; const float* lb2 = (const float*)d_in[15];
    const float* lw3 = (const float*)d_in[16]; const float* lb3 = (const float*)d_in[17];
    const float* cw  = (const float*)d_in[18]; const float* cb  = (const float*)d_in[19];
    const float* fw1 = (const float*)d_in[20]; const float* fb1 = (const float*)d_in[21];
    const float* fw2 = (const float*)d_in[22]; const float* fb2 = (const float*)d_in[23];
    const float* gw  = (const float*)d_in[24]; const float* gb  = (const float*)d_in[25];
    const float* ccm_w = (const float*)d_in[26]; const float* ccm_b = (const float*)d_in[27];
    const float* shifts = (const float*)d_in[28];
    const float* slopes = (const float*)d_in[29];
    const float* prw = (const float*)d_in[30]; const float* prb = (const float*)d_in[31];
    float* out = (float*)d_out;

    k_prep<<<24, 256>>>(sw1, sw2, sw3);
    k_conv1<<<dim3(256, 4), 256>>>(image, sw0, sb0);
    k_conv2<<<dim3(64, 2, 4), 256>>>(sb1);
    k_conv3<<<dim3(16, 4, 4), 256>>>(sb2);
    k_conv4<<<dim3(16, 2, 4), 256>>>(sb3);
    k_mid<<<dim3(32, 4), 256>>>(spw, spb, val, lw1, lb1, lw2, lb2, lw3, lb3);
    k_global<<<4, 256>>>(cw, cb, fw1, fb1, fw2, fb2);
    k_coeff<<<dim3(16, 4), 256>>>(gw, gb);
    k_slice<<<dim3(16, 16, 4), 256>>>(image, ccm_w, ccm_b, shifts, slopes, prw, prb, out);
}

// round 12
// speedup vs baseline: 1.6603x; 1.0907x over previous
#include <cuda_runtime.h>

// ---------------- scratch (device globals; no runtime alloc) ----------------
__device__ float g_x1[4*8*128*128];
__device__ float g_x2[4*16*64*64];
__device__ float g_x3[4*32*32*32];
__device__ float g_x4[4*64*16*16];
__device__ float g_splat[4*64*256];
__device__ float g_l3[4*64*256];
__device__ float g_cvec[4*64];
__device__ float g_grid[4*12*8*256];   // [b][cc 12][lb 8][y 16][x 16]
__device__ int   g_uni;                // shifts are uniform k/16 grid?
// padded transposed conv weights: [cog][coq][ CO_PER*9*CI + 4 ]
__device__ float g_w2T[4*292];         // conv2: COG=16 NCOQ=4  CO_PER=4 CI=8
__device__ float g_w3T[16*292];        // conv3: COG=32 NCOQ=16 CO_PER=2 CI=16
__device__ float g_w4T[2*16*580];      // conv4: COG=32 NCOQ=16 CO_PER=2 CI=32

// ============== prep: transpose+pad conv weights, check shift uniformity =====
template<int CI, int COG, int NCOQ, int NCO>
__device__ __forceinline__ void prep_one(const float* __restrict__ w,
                                         float* __restrict__ dst,
                                         int t, int stride) {
    constexpr int CO_PER = COG/NCOQ;
    constexpr int WSTR = CO_PER*9*CI + 4;
    for (int idx = t; idx < NCO*CI*9; idx += stride) {
        int co = idx / (CI*9);
        int rem = idx % (CI*9);
        int ci = rem / 9, kk = rem % 9;
        int cog = co / COG, coL = co % COG;
        int coq = coL / CO_PER, j = coL % CO_PER;
        dst[(cog*NCOQ + coq)*WSTR + (j*9 + kk)*CI + ci] = __ldg(&w[idx]);
    }
}
__global__ void k_prep(const float* __restrict__ w2, const float* __restrict__ w3,
                       const float* __restrict__ w4,
                       const float* __restrict__ shifts) {
    int t = blockIdx.x*256 + threadIdx.x;
    int stride = gridDim.x*256;
    prep_one<8, 16, 4, 16>(w2, g_w2T, t, stride);
    prep_one<16, 32, 16, 32>(w3, g_w3T, t, stride);
    prep_one<32, 32, 16, 64>(w4, g_w4T, t, stride);
    if (blockIdx.x == 0) {
        int tid = threadIdx.x;
        int ok = 1;
        if (tid < 48) {
            float expect = (float)(tid & 15) * 0.0625f;
            ok = (__ldg(&shifts[tid]) == expect) ? 1 : 0;
        }
        int all = __syncthreads_and(ok);
        if (tid == 0) g_uni = all;
    }
}

// ============== generic 3x3 stride-2 conv =====================================
// lanes: coq in low bits (input broadcast, weight banks spread via WSTR pad)
template<int CI, int COG, int CO_TOTAL, int IHW, int OHW, int TILE, int THREADS>
__device__ __forceinline__ void conv_run(const float* __restrict__ in,
        const float* __restrict__ wT, const float* __restrict__ bias,
        float* __restrict__ out, float* __restrict__ s_in, float* __restrict__ s_w,
        int bb, int tile, int cog) {
    constexpr int IT  = 2*TILE+1;
    constexpr int NT  = OHW/TILE;
    constexpr int POS = TILE*TILE;
    constexpr int CIP = CI + 4;
    constexpr int NCOQ = THREADS/POS;
    constexpr int CO_PER = COG/NCOQ;
    constexpr int WSTR = CO_PER*9*CI + 4;
    constexpr int NWP = NCOQ*WSTR;
    int ty0 = (tile/NT)*TILE, tx0 = (tile%NT)*TILE;
    int t = threadIdx.x;

    // weights: straight coalesced float4 copy (pre-transposed + padded)
    const float* wg = wT + (size_t)cog*NWP;
    #pragma unroll
    for (int i = t*4; i < NWP; i += THREADS*4)
        *(float4*)&s_w[i] = __ldg((const float4*)&wg[i]);
    // input tile -> smem [i][ci]
    const float* inb = in + (size_t)bb*CI*IHW*IHW;
    #pragma unroll
    for (int k = t; k < IT*IT*CI; k += THREADS) {
        int ci = k / (IT*IT);
        int i  = k % (IT*IT);
        int iy = 2*ty0 - 1 + i/IT;
        int ix = 2*tx0 - 1 + i%IT;
        float v = 0.f;
        if (iy >= 0 && iy < IHW && ix >= 0 && ix < IHW)
            v = __ldg(&inb[(size_t)ci*IHW*IHW + (size_t)iy*IHW + ix]);
        s_in[i*CIP + ci] = v;
    }
    __syncthreads();

    int coq = t & (NCOQ-1);
    int pos = t / NCOQ;
    int py = pos / TILE, px = pos % TILE;
    float acc[CO_PER];
    #pragma unroll
    for (int j = 0; j < CO_PER; j++) acc[j] = __ldg(&bias[cog*COG + coq*CO_PER + j]);

    #pragma unroll
    for (int c0 = 0; c0 < CI; c0 += 4) {
        #pragma unroll
        for (int ky = 0; ky < 3; ky++) {
            const float* rp = s_in + ((2*py+ky)*IT + 2*px)*CIP + c0;
            float4 i0 = *(const float4*)(rp);
            float4 i1 = *(const float4*)(rp + CIP);
            float4 i2 = *(const float4*)(rp + 2*CIP);
            #pragma unroll
            for (int j = 0; j < CO_PER; j++) {
                const float* wb = s_w + coq*WSTR + (j*9 + ky*3)*CI + c0;
                float4 w0 = *(const float4*)(wb);
                float4 w1 = *(const float4*)(wb + CI);
                float4 w2 = *(const float4*)(wb + 2*CI);
                acc[j] += i0.x*w0.x + i0.y*w0.y + i0.z*w0.z + i0.w*w0.w
                        + i1.x*w1.x + i1.y*w1.y + i1.z*w1.z + i1.w*w1.w
                        + i2.x*w2.x + i2.y*w2.y + i2.z*w2.z + i2.w*w2.w;
            }
        }
    }
    #pragma unroll
    for (int j = 0; j < CO_PER; j++) {
        int co = cog*COG + coq*CO_PER + j;
        out[(size_t)(bb*CO_TOTAL + co)*OHW*OHW + (size_t)(ty0+py)*OHW + tx0+px]
            = fmaxf(acc[j], 0.f);
    }
}

// ============== conv1: fused bilinear downsample + 3x3 s2 conv ================
__global__ void __launch_bounds__(256) k_conv1(const float* __restrict__ im,
        const float* __restrict__ w, const float* __restrict__ bias) {
    constexpr int TILE = 8, IT = 17, NT = 16;
    constexpr int TPC = 32, OPT = 2;
    __shared__ float s_in[IT*IT*4];
    __shared__ float s_w[8*3*9];
    int bb = blockIdx.y;
    int tile = blockIdx.x;
    int ty0 = (tile/NT)*TILE, tx0 = (tile%NT)*TILE;
    int t = threadIdx.x;
    if (t < 216) s_w[t] = __ldg(&w[t]);
    const float* imb = im + (size_t)bb * 3 * 1048576;
    #pragma unroll
    for (int k = t; k < 289*3; k += 256) {
        int ci = k / 289, i = k % 289;
        int iy = 2*ty0 - 1 + i/IT;
        int ix = 2*tx0 - 1 + i%IT;
        float v = 0.f;
        if (iy >= 0 && iy < 256 && ix >= 0 && ix < 256) {
            const float4* p = (const float4*)(imb + (size_t)ci*1048576 + (size_t)(4*iy+1)*1024) + ix;
            float4 r1 = __ldg(p);
            float4 r2 = __ldg(p + 256);
            v = 0.25f*(r1.y + r1.z + r2.y + r2.z);
        }
        s_in[i*4 + ci] = v;
    }
    __syncthreads();
    int co = t / TPC;
    int pbase = t % TPC;
    float acc[OPT];
    #pragma unroll
    for (int k = 0; k < OPT; k++) acc[k] = bias[co];
    const float* wc = s_w + co*27;
    float4 wk[9];
    #pragma unroll
    for (int k = 0; k < 9; k++) {
        wk[k].x = wc[k]; wk[k].y = wc[9+k]; wk[k].z = wc[18+k]; wk[k].w = 0.f;
    }
    #pragma unroll
    for (int k = 0; k < OPT; k++) {
        int p = pbase + k*TPC;
        int py = p/TILE, px = p%TILE;
        #pragma unroll
        for (int ky = 0; ky < 3; ky++)
        #pragma unroll
        for (int kx = 0; kx < 3; kx++) {
            float4 v = *(const float4*)&s_in[((2*py+ky)*IT + 2*px+kx)*4];
            float4 wv = wk[ky*3+kx];
            acc[k] += v.x*wv.x + v.y*wv.y + v.z*wv.z;
        }
    }
    float* outb = g_x1 + (size_t)bb*8*128*128;
    #pragma unroll
    for (int k = 0; k < OPT; k++) {
        int p = pbase + k*TPC;
        outb[(size_t)co*16384 + (size_t)(ty0+p/TILE)*128 + tx0 + p%TILE] = fmaxf(acc[k], 0.f);
    }
}

// ============== conv2..4 =====================================================
__global__ void __launch_bounds__(256) k_conv2(const float* __restrict__ b) {
    __shared__ float s_in[289*12];
    __shared__ float s_w[4*292];
    conv_run<8, 16, 16, 128, 64, 8, 256>(g_x1, g_w2T, b, g_x2, s_in, s_w,
                                         blockIdx.z, blockIdx.x, 0);
}
__global__ void __launch_bounds__(256) k_conv3(const float* __restrict__ b) {
    __shared__ float s_in[81*20];
    __shared__ float s_w[16*292];
    conv_run<16, 32, 32, 64, 32, 4, 256>(g_x2, g_w3T, b, g_x3, s_in, s_w,
                                         blockIdx.z, blockIdx.x, 0);
}
__global__ void __launch_bounds__(256) k_conv4(const float* __restrict__ b) {
    __shared__ float s_in[81*36];
    __shared__ float s_w[16*580];
    conv_run<32, 32, 64, 32, 16, 4, 256>(g_x3, g_w4T, b, g_x4, s_in, s_w,
                                         blockIdx.z, blockIdx.x, blockIdx.y);
}

// ============== mid: splat + local MLP, 8 positions/block, smem weights ======
__global__ void __launch_bounds__(256) k_mid(
        const float* __restrict__ spw, const float* __restrict__ spb,
        const float* __restrict__ val,
        const float* __restrict__ lw1, const float* __restrict__ lb1,
        const float* __restrict__ lw2, const float* __restrict__ lb2,
        const float* __restrict__ lw3, const float* __restrict__ lb3) {
    __shared__ float s_w[8192];                 // 32 KB weight stage
    __shared__ float As[8*68], A2[8*68];        // acts transposed [p][ch]
    __shared__ float Bf[8*132], Cf[8*132];
    int bb = blockIdx.y;
    int pos0 = blockIdx.x * 8;
    int t = threadIdx.x;
    int p = t & 7, oct = t >> 3;                // 32 octs

    for (int i = t*4; i < 4096; i += 1024)
        *(float4*)&s_w[i] = __ldg((const float4*)&spw[i]);
    for (int i = t; i < 512; i += 256) {
        int ci = i >> 3, pp = i & 7;
        As[pp*68 + ci] = __ldg(&g_x4[bb*16384 + ci*256 + pos0 + pp]);
    }
    __syncthreads();
    float vb = __ldg(&val[bb]);

    #pragma unroll
    for (int j = 0; j < 2; j++) {
        int ch = oct*2 + j;
        float acc = __ldg(&spb[ch]) + vb;
        #pragma unroll
        for (int i = 0; i < 64; i += 4) {
            float4 a = *(const float4*)&As[p*68 + i];
            float4 wv = *(const float4*)&s_w[ch*64 + i];
            acc += a.x*wv.x + a.y*wv.y + a.z*wv.z + a.w*wv.w;
        }
        A2[p*68 + ch] = acc;
        g_splat[(bb*64 + ch)*256 + pos0 + p] = acc;
    }
    __syncthreads();

    for (int i = t*4; i < 8192; i += 1024)
        *(float4*)&s_w[i] = __ldg((const float4*)&lw1[i]);
    __syncthreads();
    #pragma unroll
    for (int j = 0; j < 4; j++) {
        int ch = oct*4 + j;
        float acc = __ldg(&lb1[ch]);
        #pragma unroll
        for (int i = 0; i < 64; i += 4) {
            float4 a = *(const float4*)&A2[p*68 + i];
            float4 wv = *(const float4*)&s_w[ch*64 + i];
            acc += a.x*wv.x + a.y*wv.y + a.z*wv.z + a.w*wv.w;
        }
        Bf[p*132 + ch] = fmaxf(acc, 0.f);
    }
    __syncthreads();

    for (int half = 0; half < 2; half++) {
        for (int i = t*4; i < 8192; i += 1024)
            *(float4*)&s_w[i] = __ldg((const float4*)&lw2[half*8192 + i]);
        __syncthreads();
        if ((oct >> 4) == half) {
            int octl = oct & 15;
            #pragma unroll
            for (int j = 0; j < 4; j++) {
                int ch = half*64 + octl*4 + j;
                float acc = __ldg(&lb2[ch]);
                #pragma unroll
                for (int i = 0; i < 128; i += 4) {
                    float4 a = *(const float4*)&Bf[p*132 + i];
                    float4 wv = *(const float4*)&s_w[(octl*4 + j)*128 + i];
                    acc += a.x*wv.x + a.y*wv.y + a.z*wv.z + a.w*wv.w;
                }
                Cf[p*132 + ch] = fmaxf(acc, 0.f);
            }
        }
        __syncthreads();
    }

    for (int i = t*4; i < 8192; i += 1024)
        *(float4*)&s_w[i] = __ldg((const float4*)&lw3[i]);
    __syncthreads();
    #pragma unroll
    for (int j = 0; j < 2; j++) {
        int ch = oct*2 + j;
        float acc = __ldg(&lb3[ch]);
        #pragma unroll
        for (int i = 0; i < 128; i += 4) {
            float4 a = *(const float4*)&Cf[p*132 + i];
            float4 wv = *(const float4*)&s_w[ch*128 + i];
            acc += a.x*wv.x + a.y*wv.y + a.z*wv.z + a.w*wv.w;
        }
        g_l3[(bb*64 + ch)*256 + pos0 + p] = fmaxf(acc, 0.f);
    }
}

// ============== global path ===================================================
__global__ void __launch_bounds__(256) k_global(
        const float* __restrict__ cw,  const float* __restrict__ cb,
        const float* __restrict__ fw1, const float* __restrict__ fb1,
        const float* __restrict__ fw2, const float* __restrict__ fb2) {
    __shared__ float c4[4*64], cp[64], f1[64];
    int bb = blockIdx.x;
    int t = threadIdx.x;
    const float* sp = g_splat + bb*64*256;
    int oc = t >> 6, idx = t & 63;
    int gy2 = idx >> 3, gx2 = idx & 7;
    int pos = (2*gy2)*16 + 2*gx2;
    float acc = cb[oc];
    for (int i = 0; i < 64; i++) acc = fmaf(cw[oc*64+i], sp[i*256+pos], acc);
    c4[oc*64 + idx] = fmaxf(acc, 0.f);
    __syncthreads();
    if (t < 64) {
        int oc2 = t >> 4, py = (t >> 2) & 3, px = t & 3;
        cp[t] = 0.25f*(c4[oc2*64 + (2*py)*8 + 2*px]   + c4[oc2*64 + (2*py)*8 + 2*px+1] +
                       c4[oc2*64 + (2*py+1)*8 + 2*px] + c4[oc2*64 + (2*py+1)*8 + 2*px+1]);
    }
    __syncthreads();
    if (t < 64) {
        float a2 = fb1[t];
        for (int i = 0; i < 64; i++) a2 = fmaf(fw1[t*64+i], cp[i], a2);
        f1[t] = fmaxf(a2, 0.f);
    }
    __syncthreads();
    if (t < 64) {
        float a2 = fb2[t];
        for (int i = 0; i < 64; i++) a2 = fmaf(fw2[t*64+i], f1[i], a2);
        g_cvec[bb*64 + t] = fmaxf(a2, 0.f);
    }
}

// ============== coeff: fused=relu(c+loc); pw 64->96; write grid ==============
__global__ void __launch_bounds__(256) k_coeff(const float* __restrict__ gw,
                                               const float* __restrict__ gb) {
    __shared__ float s_gw[6144];
    __shared__ float fused[16*68];              // [p][ch]
    int tl = blockIdx.x;
    int bb = blockIdx.y;
    int t = threadIdx.x;
    for (int i = t*4; i < 6144; i += 1024)
        *(float4*)&s_gw[i] = __ldg((const float4*)&gw[i]);
    const float* l3p = g_l3 + bb*64*256;
    const float* cv = g_cvec + bb*64;
    for (int o = t; o < 1024; o += 256) {
        int ch = o >> 4, p = o & 15;
        fused[p*68 + ch] = fmaxf(cv[ch] + l3p[ch*256 + tl*16 + p], 0.f);
    }
    __syncthreads();
    for (int o = t; o < 1536; o += 256) {
        int och = o >> 4, p = o & 15;
        float acc = __ldg(&gb[och]);
        #pragma unroll
        for (int i = 0; i < 64; i += 4) {
            float4 a = *(const float4*)&fused[p*68 + i];
            float4 wv = *(const float4*)&s_gw[och*64 + i];
            acc += a.x*wv.x + a.y*wv.y + a.z*wv.z + a.w*wv.w;
        }
        int lb = och / 12, cc = och % 12;
        g_grid[((bb*12 + cc)*8 + lb)*256 + tl*16 + p] = acc;
    }
}

// ============== fused guide + bilateral slice =================================
__global__ void __launch_bounds__(256) k_slice(
        const float* __restrict__ im,
        const float* __restrict__ ccm_w, const float* __restrict__ ccm_b,
        const float* __restrict__ shifts, const float* __restrict__ slopes,
        const float* __restrict__ prw, const float* __restrict__ prb,
        float* __restrict__ out) {
    int bx = blockIdx.x, by = blockIdx.y, bb = blockIdx.z;
    __shared__ float sg[864];               // [cell(j*3+k)][z][c12]
    __shared__ float gy[2][4*72*4];         // double-buffered y-interp tables
    __shared__ float s_ccm[9], s_ccmb[3], s_prw[3], s_prb[1];
    __shared__ float s_sh[48];
    __shared__ float s_cs[3][17], s_csh[3][17];
    int t = threadIdx.x;

    const float* gr = g_grid + (size_t)bb * 12 * 8 * 256;
    for (int k = t; k < 864; k += 256) {
        int c = k % 12;
        int z = (k / 12) % 8;
        int cell = k / 96;
        int j = cell / 3, kx = cell % 3;
        int yi = min(max(by - 1 + j, 0), 15);
        int xi = min(max(bx - 1 + kx, 0), 15);
        sg[k] = gr[(c*8 + z)*256 + yi*16 + xi];
    }
    if (t < 9)               s_ccm[t] = ccm_w[t];
    if (t >= 16 && t < 19)   s_ccmb[t-16] = ccm_b[t-16];
    if (t >= 32 && t < 80)   s_sh[t-32] = shifts[t-32];
    if (t >= 96 && t < 99)   s_prw[t-96] = prw[t-96];
    if (t == 102)            s_prb[0] = prb[0];
    if (t >= 104 && t < 107) {
        int c = t - 104;
        float cs = 0.f, csh = 0.f;
        s_cs[c][0] = 0.f; s_csh[c][0] = 0.f;
        #pragma unroll
        for (int k = 0; k < 16; k++) {
            float s = slopes[c*16+k], h = shifts[c*16+k];
            cs += s; csh += s*h;
            s_cs[c][k+1] = cs; s_csh[c][k+1] = csh;
        }
    }
    __syncthreads();

    int uni = g_uni;
    int g = t >> 6;
    int lx = t & 63;
    int x = bx*64 + lx;
    float cxv = ((float)x + 0.5f) * (1.0f/64.0f) - 0.5f;
    float wx = cxv - floorf(cxv);
    int k0 = (int)floorf(cxv) - (bx - 1);
    const float* imb = im + (size_t)bb * 3 * 1048576;
    float* outb = out + (size_t)bb * 3 * 1048576;

    for (int r = 0; r < 16; r++) {
        int buf = r & 1;
        int y = by*64 + g + 4*r;
        float cyv = ((float)y + 0.5f) * (1.0f/64.0f) - 0.5f;
        float wy = cyv - floorf(cyv);
        int j0 = (int)floorf(cyv) - (by - 1);

        for (int e = lx; e < 72; e += 64) {
            int cellx = e / 24;
            int z = (e / 3) % 8;
            int v = e % 3;
            float4 a = ((const float4*)sg)[((j0*3 + cellx)*8 + z)*3 + v];
            float4 b4 = ((const float4*)sg)[(((j0+1)*3 + cellx)*8 + z)*3 + v];
            float4 res;
            res.x = fmaf(wy, b4.x - a.x, a.x);
            res.y = fmaf(wy, b4.y - a.y, a.y);
            res.z = fmaf(wy, b4.z - a.z, a.z);
            res.w = fmaf(wy, b4.w - a.w, a.w);
            ((float4*)gy[buf])[g*72 + e] = res;
        }
        asm volatile("bar.sync %0, %1;" :: "r"(g+1), "r"(64) : "memory");

        size_t poff = (size_t)y * 1024 + x;
        float i0 = __ldg(&imb[poff]);
        float i1 = __ldg(&imb[poff + 1048576]);
        float i2 = __ldg(&imb[poff + 2097152]);

        float q0 = s_ccmb[0] + s_ccm[0]*i0 + s_ccm[1]*i1 + s_ccm[2]*i2;
        float q1 = s_ccmb[1] + s_ccm[3]*i0 + s_ccm[4]*i1 + s_ccm[5]*i2;
        float q2 = s_ccmb[2] + s_ccm[6]*i0 + s_ccm[7]*i1 + s_ccm[8]*i2;
        float tt[3];
        float qv[3] = {q0, q1, q2};
        if (uni) {
            #pragma unroll
            for (int c = 0; c < 3; c++) {
                float gv = qv[c];
                int p = (int)ceilf(gv * 16.f);
                p = min(16, max(0, p));
                tt[c] = fmaf(gv, s_cs[c][p], -s_csh[c][p]);
            }
        } else {
            #pragma unroll
            for (int c = 0; c < 3; c++) {
                const float* H = &s_sh[c*16];
                float gv = qv[c];
                int p = (gv > H[7]) ? 8 : 0;
                p += (gv > H[p+3]) ? 4 : 0;
                p += (gv > H[p+1]) ? 2 : 0;
                p += (gv > H[p])   ? 1 : 0;
                p += (gv > H[p])   ? 1 : 0;
                tt[c] = fmaf(gv, s_cs[c][p], -s_csh[c][p]);
            }
        }
        float gg = s_prb[0] + s_prw[0]*tt[0] + s_prw[1]*tt[1] + s_prw[2]*tt[2];
        float guide = fminf(fmaxf(gg, 0.f), 1.f);

        float cz = guide * 8.0f - 0.5f;
        float z0f = floorf(cz);
        float wz = cz - z0f;
        int z0 = (int)z0f;
        int zi0 = min(max(z0, 0), 7);
        int zi1 = min(max(z0 + 1, 0), 7);

        float w00 = (1.f-wx)*(1.f-wz), w01 = (1.f-wx)*wz;
        float w10 = wx*(1.f-wz),       w11 = wx*wz;

        const float4* T = (const float4*)gy[buf];
        int bA = (g*3 + k0)*8;
        int bB = bA + 8;
        int iA0 = (bA + zi0)*3, iA1 = (bA + zi1)*3;
        int iB0 = (bB + zi0)*3, iB1 = (bB + zi1)*3;

        float a0,a1,a2,a3,a4,a5,a6,a7,a8,a9,a10,a11;
        {
            float4 v0 = T[iA0], v1 = T[iA1], v2 = T[iB0], v3 = T[iB1];
            a0 = w00*v0.x + w01*v1.x + w10*v2.x + w11*v3.x;
            a1 = w00*v0.y + w01*v1.y + w10*v2.y + w11*v3.y;
            a2 = w00*v0.z + w01*v1.z + w10*v2.z + w11*v3.z;
            a3 = w00*v0.w + w01*v1.w + w10*v2.w + w11*v3.w;
        }
        {
            float4 v0 = T[iA0+1], v1 = T[iA1+1], v2 = T[iB0+1], v3 = T[iB1+1];
            a4 = w00*v0.x + w01*v1.x + w10*v2.x + w11*v3.x;
            a5 = w00*v0.y + w01*v1.y + w10*v2.y + w11*v3.y;
            a6 = w00*v0.z + w01*v1.z + w10*v2.z + w11*v3.z;
            a7 = w00*v0.w + w01*v1.w + w10*v2.w + w11*v3.w;
        }
        {
            float4 v0 = T[iA0+2], v1 = T[iA1+2], v2 = T[iB0+2], v3 = T[iB1+2];
            a8  = w00*v0.x + w01*v1.x + w10*v2.x + w11*v3.x;
            a9  = w00*v0.y + w01*v1.y + w10*v2.y + w11*v3.y;
            a10 = w00*v0.z + w01*v1.z + w10*v2.z + w11*v3.z;
            a11 = w00*v0.w + w01*v1.w + w10*v2.w + w11*v3.w;
        }
        outb[poff]           = fmaf(a0, i0, fmaf(a1, i1, fmaf(a2,  i2, a3)));
        outb[poff + 1048576] = fmaf(a4, i0, fmaf(a5, i1, fmaf(a6,  i2, a7)));
        outb[poff + 2097152] = fmaf(a8, i0, fmaf(a9, i1, fmaf(a10, i2, a11)));
    }
}

// ---------------- launcher ---------------------------------------------------
extern "C" void kernel_launch(void* const* d_in, const int* in_sizes, int n_in,
                              void* d_out, int out_size) {
    const float* image = (const float*)d_in[0];
    const float* val   = (const float*)d_in[1];
    const float* sw0 = (const float*)d_in[2];  const float* sb0 = (const float*)d_in[3];
    const float* sw1 = (const float*)d_in[4];  const float* sb1 = (const float*)d_in[5];
    const float* sw2 = (const float*)d_in[6];  const float* sb2 = (const float*)d_in[7];
    const float* sw3 = (const float*)d_in[8];  const float* sb3 = (const float*)d_in[9];
    const float* spw = (const float*)d_in[10]; const float* spb = (const float*)d_in[11];
    const float* lw1 = (const float*)d_in[12]; const float* lb1 = (const float*)d_in[13];
    const float* lw2 = (const float*)d_in[14]; const float* lb2 = (const float*)d_in[15];
    const float* lw3 = (const float*)d_in[16]; const float* lb3 = (const float*)d_in[17];
    const float* cw  = (const float*)d_in[18]; const float* cb  = (const float*)d_in[19];
    const float* fw1 = (const float*)d_in[20]; const float* fb1 = (const float*)d_in[21];
    const float* fw2 = (const float*)d_in[22]; const float* fb2 = (const float*)d_in[23];
    const float* gw  = (const float*)d_in[24]; const float* gb  = (const float*)d_in[25];
    const float* ccm_w = (const float*)d_in[26]; const float* ccm_b = (const float*)d_in[27];
    const float* shifts = (const float*)d_in[28];
    const float* slopes = (const float*)d_in[29];
    const float* prw = (const float*)d_in[30]; const float* prb = (const float*)d_in[31];
    float* out = (float*)d_out;

    k_prep<<<24, 256>>>(sw1, sw2, sw3, shifts);
    k_conv1<<<dim3(256, 4), 256>>>(image, sw0, sb0);
    k_conv2<<<dim3(64, 1, 4), 256>>>(sb1);
    k_conv3<<<dim3(64, 1, 4), 256>>>(sb2);
    k_conv4<<<dim3(16, 2, 4), 256>>>(sb3);
    k_mid<<<dim3(32, 4), 256>>>(spw, spb, val, lw1, lb1, lw2, lb2, lw3, lb3);
    k_global<<<4, 256>>>(cw, cb, fw1, fb1, fw2, fb2);
    k_coeff<<<dim3(16, 4), 256>>>(gw, gb);
    k_slice<<<dim3(16, 16, 4), 256>>>(image, ccm_w, ccm_b, shifts, slopes, prw, prb, out);
}